// round 12
// baseline (speedup 1.0000x reference)
#include <cuda_runtime.h>
#include <cuda_fp16.h>
#include <cstdint>
#include <math.h>

#define NTOK 16384
#define DM   1024
#define DFFN 4096
#define NE   8
#define TOPK 2
#define NSLOT (NTOK * TOPK)

#define BM 128
#define BN 128
#define BK 32
#define STAGES 4
#define THREADS 128   // both GEMMs: 4 warps, grid 2x2, warp tile 64x64

// ---------------- device scratch (static globals: allocation-free) ----------
__device__ int   g_cnt[NE];
__device__ int   g_tok[NE * NTOK];
__device__ float g_wt [NE * NTOK];

// padded by BM rows so tile-overhang reads stay in bounds (never written -> 0)
__device__ __align__(16) __half XGH[(size_t)(NSLOT + BM) * DM];
__device__ __align__(16) __half HH [(size_t)(NSLOT + BM) * DFFN];
__device__ __align__(16) __half W1H[(size_t)NE * DM * DFFN];
__device__ __align__(16) __half W2H[(size_t)NE * DFFN * DM];

// ---------------- asm helpers ----------------------------------------------
__device__ __forceinline__ void cp16(uint32_t dst, const void* src) {
    asm volatile("cp.async.cg.shared.global [%0], [%1], 16;" :: "r"(dst), "l"(src));
}
#define CP_COMMIT() asm volatile("cp.async.commit_group;" ::: "memory")
#define CP_WAIT(n)  asm volatile("cp.async.wait_group %0;" :: "n"(n) : "memory")

#define LDSM_X4(r0, r1, r2, r3, addr) \
    asm volatile("ldmatrix.sync.aligned.m8n8.x4.shared.b16 {%0,%1,%2,%3}, [%4];" \
                 : "=r"(r0), "=r"(r1), "=r"(r2), "=r"(r3) : "r"(addr))
#define LDSM_X4T(r0, r1, r2, r3, addr) \
    asm volatile("ldmatrix.sync.aligned.m8n8.x4.trans.shared.b16 {%0,%1,%2,%3}, [%4];" \
                 : "=r"(r0), "=r"(r1), "=r"(r2), "=r"(r3) : "r"(addr))

__device__ __forceinline__ void mma_f16(float* c, const uint32_t* a,
                                        uint32_t b0, uint32_t b1) {
    asm volatile(
        "mma.sync.aligned.m16n8k16.row.col.f32.f16.f16.f32 "
        "{%0,%1,%2,%3}, {%4,%5,%6,%7}, {%8,%9}, {%0,%1,%2,%3};"
        : "+f"(c[0]), "+f"(c[1]), "+f"(c[2]), "+f"(c[3])
        : "r"(a[0]), "r"(a[1]), "r"(a[2]), "r"(a[3]), "r"(b0), "r"(b1));
}

// vector reduction (sm_90+): one instruction adds 2 floats to gmem
__device__ __forceinline__ void red_add_v2(float* addr, float y0, float y1) {
    asm volatile("red.global.add.v2.f32 [%0], {%1, %2};"
                 :: "l"(addr), "f"(y0), "f"(y1) : "memory");
}

// ---------------- smem layout: per stage 16KB ------------------------------
// A 128x32 fp16 (8KB), B 32x128 (8KB); 4 stages = 64KB/CTA, 2 CTA/SM
#define STAGE_BYTES 16384u
#define SA(s)  ((uint32_t)(s) * STAGE_BYTES)
#define SB(s)  ((uint32_t)(s) * STAGE_BYTES + 8192u)
#define SMEM_SZ (STAGES * 16384)

// A: row pitch 64B (4x16B chunks), swizzle chunk ^= (row>>1)&3 (conflict-free)
__device__ __forceinline__ uint32_t a_off(int row, int ch) {
    return (uint32_t)(row * 64 + ((ch ^ ((row >> 1) & 3)) << 4));
}
// B: row pitch 256B (16x16B chunks), swizzle low3 of chunk ^= k&7
__device__ __forceinline__ uint32_t b_off(int k, int ch) {
    return (uint32_t)(k * 256 + (((ch & ~7) | ((ch ^ k) & 7)) << 4));
}

__device__ __forceinline__ float gelu_f(float v) {
    return 0.5f * v * (1.f + erff(v * 0.70710678118654752440f));
}
__device__ __forceinline__ uint32_t pack_h2(float a, float b) {
    __half x = __float2half_rn(a), y = __float2half_rn(b);
    return (uint32_t)__half_as_ushort(x) | ((uint32_t)__half_as_ushort(y) << 16);
}
__device__ __forceinline__ int expert_off(int e) {
    int off = 0;
#pragma unroll
    for (int i = 0; i < NE; i++) if (i < e) off += g_cnt[i];
    return off;
}

// ---------------- stage loader (128 threads) ---------------------------------
__device__ __forceinline__ void load_stage(
    uint32_t sb, int stage, const __half* __restrict__ A, size_t lda,
    const __half* __restrict__ B, size_t ldb,
    size_t arow0, int k0, int n0, int tid) {
#pragma unroll
    for (int i = 0; i < 4; i++) {           // A: 512 chunks
        int ca = tid + 128 * i;
        int row = ca >> 2, ch = ca & 3;
        size_t gsrc = (arow0 + row) * lda + k0 + ch * 8;
        cp16(sb + SA(stage) + a_off(row, ch), A + gsrc);
    }
#pragma unroll
    for (int i = 0; i < 4; i++) {           // B: 512 chunks
        int cb = tid + 128 * i;
        int k = cb >> 4, ch = cb & 15;
        size_t gsrc = (size_t)(k0 + k) * ldb + n0 + ch * 8;
        cp16(sb + SB(stage) + b_off(k, ch), B + gsrc);
    }
}

// ---------------- per-stage compute: warp tile 64x64, software-pipelined ----
// [ah(h0)+bf(h0) -> MMA h0 nt0..3 -> prefetch ah(h1) -> MMA h0 nt4..7
//  -> bf(h1) -> MMA h1 all]  : every LDSM group covered by >=16 MMAs in flight
__device__ __forceinline__ void compute_stage(
    uint32_t sb, int stage, float acc[4][8][4], int wm, int wn, int lane) {
    uint32_t sa = sb + SA(stage);
    uint32_t sbB = sb + SB(stage);
    int l15 = lane & 15, l16 = lane >> 4;
    uint32_t ah[4][4], ah2[4][4], bf[8][2];

    // half-0 A fragments
#pragma unroll
    for (int mt = 0; mt < 4; mt++) {
        int row = wm * 64 + mt * 16 + l15;
        LDSM_X4(ah[mt][0], ah[mt][1], ah[mt][2], ah[mt][3],
                sa + a_off(row, l16));
    }
    // half-0 B fragments
#pragma unroll
    for (int ng = 0; ng < 4; ng++) {
        uint32_t off = b_off(l15, wn * 8 + ng * 2 + l16);
        LDSM_X4T(bf[2 * ng][0], bf[2 * ng][1],
                 bf[2 * ng + 1][0], bf[2 * ng + 1][1], sbB + off);
    }
    // MMA half-0, nt 0..3
#pragma unroll
    for (int mt = 0; mt < 4; mt++)
#pragma unroll
        for (int nt = 0; nt < 4; nt++)
            mma_f16(acc[mt][nt], ah[mt], bf[nt][0], bf[nt][1]);
    // prefetch half-1 A under the MMAs
#pragma unroll
    for (int mt = 0; mt < 4; mt++) {
        int row = wm * 64 + mt * 16 + l15;
        LDSM_X4(ah2[mt][0], ah2[mt][1], ah2[mt][2], ah2[mt][3],
                sa + a_off(row, 2 + l16));
    }
    // MMA half-0, nt 4..7
#pragma unroll
    for (int mt = 0; mt < 4; mt++)
#pragma unroll
        for (int nt = 4; nt < 8; nt++)
            mma_f16(acc[mt][nt], ah[mt], bf[nt][0], bf[nt][1]);
    // half-1 B fragments (bf dead after last use above)
#pragma unroll
    for (int ng = 0; ng < 4; ng++) {
        uint32_t off = b_off(16 + l15, wn * 8 + ng * 2 + l16);
        LDSM_X4T(bf[2 * ng][0], bf[2 * ng][1],
                 bf[2 * ng + 1][0], bf[2 * ng + 1][1], sbB + off);
    }
    // MMA half-1, all nt
#pragma unroll
    for (int mt = 0; mt < 4; mt++)
#pragma unroll
        for (int nt = 0; nt < 8; nt++)
            mma_f16(acc[mt][nt], ah2[mt], bf[nt][0], bf[nt][1]);
}

// ---------------- launch 0: zero output + counters ---------------------------
__global__ void zero_kernel(float* __restrict__ out) {
    size_t i = (size_t)blockIdx.x * blockDim.x + threadIdx.x;
    const size_t tot4 = (size_t)NTOK * DM / 4;
    if (i < tot4) ((float4*)out)[i] = make_float4(0.f, 0.f, 0.f, 0.f);
    if (i < NE) g_cnt[i] = 0;
}

// ---------------- launch 1: gating (one warp / token) ------------------------
__global__ __launch_bounds__(256) void gating_kernel(
    const float* __restrict__ x, const float* __restrict__ gW,
    const float* __restrict__ gb, float* __restrict__ out_topi, int write_topi) {
    int warp = (int)((blockIdx.x * blockDim.x + threadIdx.x) >> 5);
    int lane = threadIdx.x & 31;
    if (warp >= NTOK) return;
    const float* xr = x + (size_t)warp * DM;
    float acc[NE];
#pragma unroll
    for (int e = 0; e < NE; e++) acc[e] = 0.f;
    for (int d = lane; d < DM; d += 32) {
        float xv = xr[d];
        const float4* w4 = (const float4*)(gW + d * NE);
        float4 wa = w4[0], wb = w4[1];
        acc[0] += xv * wa.x; acc[1] += xv * wa.y;
        acc[2] += xv * wa.z; acc[3] += xv * wa.w;
        acc[4] += xv * wb.x; acc[5] += xv * wb.y;
        acc[6] += xv * wb.z; acc[7] += xv * wb.w;
    }
#pragma unroll
    for (int e = 0; e < NE; e++)
#pragma unroll
        for (int o = 16; o > 0; o >>= 1)
            acc[e] += __shfl_xor_sync(0xffffffffu, acc[e], o);
    if (lane == 0) {
        float v0 = -1e30f, v1 = -1e30f; int i0 = 0, i1 = 0;
#pragma unroll
        for (int e = 0; e < NE; e++) {
            float l = acc[e] + gb[e];
            if (l > v0)      { v1 = v0; i1 = i0; v0 = l; i0 = e; }
            else if (l > v1) { v1 = l;  i1 = e; }
        }
        float e1 = expf(v1 - v0);
        float s  = 1.f + e1;
        float w0 = 1.f / s, w1 = e1 / s;
        int p0 = atomicAdd(&g_cnt[i0], 1);
        g_tok[i0 * NTOK + p0] = warp; g_wt[i0 * NTOK + p0] = w0;
        int p1 = atomicAdd(&g_cnt[i1], 1);
        g_tok[i1 * NTOK + p1] = warp; g_wt[i1 * NTOK + p1] = w1;
        if (write_topi) {
            out_topi[warp * 2 + 0] = (float)i0;
            out_topi[warp * 2 + 1] = (float)i1;
        }
    }
}

// ---------------- launch 2: fused prep (weight fp16 convert + gather) --------
__global__ __launch_bounds__(256) void prep_kernel(
    const float* __restrict__ x, const float* __restrict__ W1,
    const float* __restrict__ W2) {
    const size_t n4 = (size_t)NE * DM * DFFN / 4;
    if (blockIdx.y < 2) {                       // weight fp16 convert
        size_t i = (size_t)blockIdx.x * blockDim.x + threadIdx.x;
        if (i >= n4) return;
        const float* src = blockIdx.y ? W2 : W1;
        __half* dh = blockIdx.y ? W2H : W1H;
        float4 v = ((const float4*)src)[i];
        uint2 hh;
        hh.x = pack_h2(v.x, v.y); hh.y = pack_h2(v.z, v.w);
        ((uint2*)dh)[i] = hh;
    } else {                                    // gather routed rows -> fp16
        int e = blockIdx.x >> 12;               // 4096 x-blocks per expert
        int cnt = g_cnt[e], off = expert_off(e);
        int rbase = (blockIdx.x & 4095) * 4;
#pragma unroll
        for (int rr = 0; rr < 4; rr++) {
            int r = rbase + rr;
            if (r >= cnt) continue;
            int tok = g_tok[e * NTOK + r];
            float4 v = ((const float4*)(x + (size_t)tok * DM))[threadIdx.x];
            uint2 hh;
            hh.x = pack_h2(v.x, v.y); hh.y = pack_h2(v.z, v.w);
            ((uint2*)(XGH + (size_t)(off + r) * DM))[threadIdx.x] = hh;
        }
    }
}

// ---------------- launch 3: GEMM1  h = fp16(gelu(xg @ W1 + b1)) --------------
__global__ __launch_bounds__(THREADS, 2) void gemm1_mma(const float* __restrict__ b1) {
    extern __shared__ char smem[];
    int e = blockIdx.z;
    int rows = g_cnt[e], off = expert_off(e);
    int row0 = blockIdx.y * BM;
    if (row0 >= rows) return;
    int n0 = blockIdx.x * BN;
    uint32_t sb = (uint32_t)__cvta_generic_to_shared(smem);
    int tid = threadIdx.x, lane = tid & 31, wid = tid >> 5;
    int wm = wid & 1, wn = wid >> 1;
    const __half* B = W1H + (size_t)e * DM * DFFN;
    size_t arow0 = (size_t)off + row0;

    float acc[4][8][4];
#pragma unroll
    for (int a = 0; a < 4; a++)
#pragma unroll
        for (int b = 0; b < 8; b++)
#pragma unroll
            for (int c = 0; c < 4; c++) acc[a][b][c] = 0.f;

    const int nk = DM / BK;  // 32
#pragma unroll
    for (int p = 0; p < STAGES - 1; p++) {
        load_stage(sb, p, XGH, DM, B, DFFN, arow0, p * BK, n0, tid);
        CP_COMMIT();
    }
    for (int t = 0; t < nk; t++) {
        CP_WAIT(STAGES - 2);
        __syncthreads();
        int nx = t + STAGES - 1;
        if (nx < nk)
            load_stage(sb, nx % STAGES, XGH, DM, B, DFFN,
                       arow0, nx * BK, n0, tid);
        CP_COMMIT();
        compute_stage(sb, t % STAGES, acc, wm, wn, lane);
    }

    const float* bias = b1 + (size_t)e * DFFN;
    int quad = lane >> 2, pair = lane & 3;
#pragma unroll
    for (int mt = 0; mt < 4; mt++) {
        int rb = row0 + wm * 64 + mt * 16 + quad;
#pragma unroll
        for (int nt = 0; nt < 8; nt++) {
            int col = n0 + wn * 64 + nt * 8 + pair * 2;
            float bs0 = __ldg(&bias[col]), bs1 = __ldg(&bias[col + 1]);
            if (rb < rows) {
                size_t o = (size_t)(off + rb) * DFFN + col;
                *(uint32_t*)(HH + o) =
                    pack_h2(gelu_f(acc[mt][nt][0] + bs0), gelu_f(acc[mt][nt][1] + bs1));
            }
            if (rb + 8 < rows) {
                size_t o = (size_t)(off + rb + 8) * DFFN + col;
                *(uint32_t*)(HH + o) =
                    pack_h2(gelu_f(acc[mt][nt][2] + bs0), gelu_f(acc[mt][nt][3] + bs1));
            }
        }
    }
}

// ---------------- launch 4: GEMM2  out[tok] += wt * (h @ W2 + b2) ------------
__global__ __launch_bounds__(THREADS, 2) void gemm2_mma(
    const float* __restrict__ b2, float* __restrict__ out) {
    extern __shared__ char smem[];
    int e = blockIdx.z;
    int rows = g_cnt[e], off = expert_off(e);
    int row0 = blockIdx.y * BM;
    if (row0 >= rows) return;
    int n0 = blockIdx.x * BN;
    uint32_t sb = (uint32_t)__cvta_generic_to_shared(smem);
    int tid = threadIdx.x, lane = tid & 31, wid = tid >> 5;
    int wm = wid & 1, wn = wid >> 1;
    const __half* B = W2H + (size_t)e * DFFN * DM;
    size_t arow0 = (size_t)off + row0;

    float acc[4][8][4];
#pragma unroll
    for (int a = 0; a < 4; a++)
#pragma unroll
        for (int b = 0; b < 8; b++)
#pragma unroll
            for (int c = 0; c < 4; c++) acc[a][b][c] = 0.f;

    const int nk = DFFN / BK;  // 128
#pragma unroll
    for (int p = 0; p < STAGES - 1; p++) {
        load_stage(sb, p, HH, DFFN, B, DM, arow0, p * BK, n0, tid);
        CP_COMMIT();
    }
    for (int t = 0; t < nk; t++) {
        CP_WAIT(STAGES - 2);
        __syncthreads();
        int nx = t + STAGES - 1;
        if (nx < nk)
            load_stage(sb, nx % STAGES, HH, DFFN, B, DM,
                       arow0, nx * BK, n0, tid);
        CP_COMMIT();
        compute_stage(sb, t % STAGES, acc, wm, wn, lane);
    }

    const float* bias = b2 + (size_t)e * DM;
    int quad = lane >> 2, pair = lane & 3;
#pragma unroll
    for (int mt = 0; mt < 4; mt++) {
        int rb = row0 + wm * 64 + mt * 16 + quad;
        int tok0 = 0, tok1 = 0; float wt0 = 0.f, wt1 = 0.f;
        if (rb < rows)     { tok0 = g_tok[e * NTOK + rb];     wt0 = g_wt[e * NTOK + rb]; }
        if (rb + 8 < rows) { tok1 = g_tok[e * NTOK + rb + 8]; wt1 = g_wt[e * NTOK + rb + 8]; }
#pragma unroll
        for (int nt = 0; nt < 8; nt++) {
            int col = n0 + wn * 64 + nt * 8 + pair * 2;
            float bs0 = __ldg(&bias[col]), bs1 = __ldg(&bias[col + 1]);
            if (rb < rows) {
                float* orow = out + (size_t)tok0 * DM + col;
                red_add_v2(orow, (acc[mt][nt][0] + bs0) * wt0,
                                 (acc[mt][nt][1] + bs1) * wt0);
            }
            if (rb + 8 < rows) {
                float* orow = out + (size_t)tok1 * DM + col;
                red_add_v2(orow, (acc[mt][nt][2] + bs0) * wt1,
                                 (acc[mt][nt][3] + bs1) * wt1);
            }
        }
    }
}

// ---------------- host -------------------------------------------------------
extern "C" void kernel_launch(void* const* d_in, const int* in_sizes, int n_in,
                              void* d_out, int out_size) {
    const float* x  = (const float*)d_in[0];
    const float* gW = (const float*)d_in[1];
    const float* gb = (const float*)d_in[2];
    const float* W1 = (const float*)d_in[3];
    const float* b1 = (const float*)d_in[4];
    const float* W2 = (const float*)d_in[5];
    const float* b2 = (const float*)d_in[6];
    float* out = (float*)d_out;
    int write_topi = (out_size >= NTOK * DM + NTOK * TOPK) ? 1 : 0;

    cudaFuncSetAttribute(gemm1_mma, cudaFuncAttributeMaxDynamicSharedMemorySize, SMEM_SZ);
    cudaFuncSetAttribute(gemm2_mma, cudaFuncAttributeMaxDynamicSharedMemorySize, SMEM_SZ);

    {   // launch 0
        size_t tot4 = (size_t)NTOK * DM / 4;
        zero_kernel<<<(int)((tot4 + 255) / 256), 256>>>(out);
    }
    // launch 1
    gating_kernel<<<(NTOK * 32) / 256, 256>>>(x, gW, gb, out + (size_t)NTOK * DM,
                                              write_topi);
    // launch 2: fused weight-convert (y=0,1) + gather (y=2)
    prep_kernel<<<dim3(32768, 3), 256>>>(x, W1, W2);
    // launch 3 (profiler slot): GEMM1, 64x64 warp tile + pipelined fragments
    gemm1_mma<<<dim3(DFFN / BN, NTOK / BM, NE), THREADS, SMEM_SZ>>>(b1);
    // launch 4: GEMM2, same compute core + v2 reductions
    gemm2_mma<<<dim3(DM / BN, NTOK / BM, NE), THREADS, SMEM_SZ>>>(b2, out);
}

// round 13
// speedup vs baseline: 1.0228x; 1.0228x over previous
#include <cuda_runtime.h>
#include <cuda_fp16.h>
#include <cstdint>
#include <math.h>

#define NTOK 16384
#define DM   1024
#define DFFN 4096
#define NE   8
#define TOPK 2
#define NSLOT (NTOK * TOPK)

#define BM 128
#define BN 128
#define BK 64
#define STAGES 3
#define THREADS1 256   // gemm1: 8 warps, grid 2x4, tile 64x32
#define THREADS2 128   // gemm2: 4 warps, grid 2x2, tile 64x64

// ---------------- device scratch (static globals: allocation-free) ----------
__device__ int   g_cnt[NE];
__device__ int   g_tok[NE * NTOK];
__device__ float g_wt [NE * NTOK];

// padded by BM rows so tile-overhang reads stay in bounds (never written -> 0)
__device__ __align__(16) __half XGH[(size_t)(NSLOT + BM) * DM];
__device__ __align__(16) __half HH [(size_t)(NSLOT + BM) * DFFN];
__device__ __align__(16) __half W1H[(size_t)NE * DM * DFFN];
__device__ __align__(16) __half W2H[(size_t)NE * DFFN * DM];

// ---------------- asm helpers ----------------------------------------------
__device__ __forceinline__ void cp16(uint32_t dst, const void* src) {
    asm volatile("cp.async.cg.shared.global [%0], [%1], 16;" :: "r"(dst), "l"(src));
}
#define CP_COMMIT() asm volatile("cp.async.commit_group;" ::: "memory")
#define CP_WAIT(n)  asm volatile("cp.async.wait_group %0;" :: "n"(n) : "memory")

#define LDSM_X4(r0, r1, r2, r3, addr) \
    asm volatile("ldmatrix.sync.aligned.m8n8.x4.shared.b16 {%0,%1,%2,%3}, [%4];" \
                 : "=r"(r0), "=r"(r1), "=r"(r2), "=r"(r3) : "r"(addr))
#define LDSM_X4T(r0, r1, r2, r3, addr) \
    asm volatile("ldmatrix.sync.aligned.m8n8.x4.trans.shared.b16 {%0,%1,%2,%3}, [%4];" \
                 : "=r"(r0), "=r"(r1), "=r"(r2), "=r"(r3) : "r"(addr))

__device__ __forceinline__ void mma_f16(float* c, const uint32_t* a,
                                        uint32_t b0, uint32_t b1) {
    asm volatile(
        "mma.sync.aligned.m16n8k16.row.col.f32.f16.f16.f32 "
        "{%0,%1,%2,%3}, {%4,%5,%6,%7}, {%8,%9}, {%0,%1,%2,%3};"
        : "+f"(c[0]), "+f"(c[1]), "+f"(c[2]), "+f"(c[3])
        : "r"(a[0]), "r"(a[1]), "r"(a[2]), "r"(a[3]), "r"(b0), "r"(b1));
}

// vector reduction (sm_90+): one instruction adds 2 floats to gmem
__device__ __forceinline__ void red_add_v2(float* addr, float y0, float y1) {
    asm volatile("red.global.add.v2.f32 [%0], {%1, %2};"
                 :: "l"(addr), "f"(y0), "f"(y1) : "memory");
}

// ---------------- smem layout: per stage 32KB ------------------------------
// A 128x64 fp16 (16KB), B 64x128 (16KB); 3 stages = 96KB/CTA, 2 CTA/SM
#define STAGE_BYTES 32768u
#define SA(s)  ((uint32_t)(s) * STAGE_BYTES)
#define SB(s)  ((uint32_t)(s) * STAGE_BYTES + 16384u)
#define SMEM_SZ (STAGES * 32768)

// A: row pitch 128B (8x16B chunks), swizzle chunk ^= row&7 (conflict-free)
__device__ __forceinline__ uint32_t a_off(int row, int ch) {
    return (uint32_t)(row * 128 + ((ch ^ (row & 7)) << 4));
}
// B: row pitch 256B (16x16B chunks), swizzle low3 of chunk ^= k&7
__device__ __forceinline__ uint32_t b_off(int k, int ch) {
    return (uint32_t)(k * 256 + (((ch & ~7) | ((ch ^ k) & 7)) << 4));
}

__device__ __forceinline__ float gelu_f(float v) {
    return 0.5f * v * (1.f + erff(v * 0.70710678118654752440f));
}
__device__ __forceinline__ uint32_t pack_h2(float a, float b) {
    __half x = __float2half_rn(a), y = __float2half_rn(b);
    return (uint32_t)__half_as_ushort(x) | ((uint32_t)__half_as_ushort(y) << 16);
}
__device__ __forceinline__ int expert_off(int e) {
    int off = 0;
#pragma unroll
    for (int i = 0; i < NE; i++) if (i < e) off += g_cnt[i];
    return off;
}

// ---------------- stage loader, templated on thread count -------------------
template <int NT>
__device__ __forceinline__ void load_stage(
    uint32_t sb, int stage, const __half* __restrict__ A, size_t lda,
    const __half* __restrict__ B, size_t ldb,
    size_t arow0, int k0, int n0, int tid) {
#pragma unroll
    for (int i = 0; i < 1024 / NT; i++) {   // A: 1024 chunks (128 rows x 8)
        int ca = tid + NT * i;
        int row = ca >> 3, ch = ca & 7;
        size_t gsrc = (arow0 + row) * lda + k0 + ch * 8;
        cp16(sb + SA(stage) + a_off(row, ch), A + gsrc);
    }
#pragma unroll
    for (int i = 0; i < 1024 / NT; i++) {   // B: 1024 chunks (64 k x 16)
        int cb = tid + NT * i;
        int k = cb >> 4, ch = cb & 15;
        size_t gsrc = (size_t)(k0 + k) * ldb + n0 + ch * 8;
        cp16(sb + SB(stage) + b_off(k, ch), B + gsrc);
    }
}

// ---------------- compute A: 8 warps, grid 2x4, warp tile 64x32 -------------
__device__ __forceinline__ void compute_stage_a(
    uint32_t sb, int stage, float acc[4][4][4], int wm, int wn, int lane) {
    uint32_t sa = sb + SA(stage);
    uint32_t sbB = sb + SB(stage);
    int l15 = lane & 15, l16 = lane >> 4;
#pragma unroll
    for (int half = 0; half < 4; half++) {      // kk = half*16, BK=64
        uint32_t ah[4][4];
#pragma unroll
        for (int mt = 0; mt < 4; mt++) {
            int row = wm * 64 + mt * 16 + l15;
            LDSM_X4(ah[mt][0], ah[mt][1], ah[mt][2], ah[mt][3],
                    sa + a_off(row, half * 2 + l16));
        }
        uint32_t bf[4][2];
        int kk = half * 16 + l15;
#pragma unroll
        for (int ng = 0; ng < 2; ng++) {
            uint32_t off = b_off(kk, wn * 4 + ng * 2 + l16);
            LDSM_X4T(bf[2 * ng][0], bf[2 * ng][1],
                     bf[2 * ng + 1][0], bf[2 * ng + 1][1], sbB + off);
        }
#pragma unroll
        for (int mt = 0; mt < 4; mt++)
#pragma unroll
            for (int nt = 0; nt < 4; nt++)
                mma_f16(acc[mt][nt], ah[mt], bf[nt][0], bf[nt][1]);
    }
}

// ---------------- compute B: 4 warps, grid 2x2, warp tile 64x64 -------------
__device__ __forceinline__ void compute_stage_b(
    uint32_t sb, int stage, float acc[4][8][4], int wm, int wn, int lane) {
    uint32_t sa = sb + SA(stage);
    uint32_t sbB = sb + SB(stage);
    int l15 = lane & 15, l16 = lane >> 4;
#pragma unroll
    for (int half = 0; half < 4; half++) {      // kk = half*16, BK=64
        uint32_t ah[4][4];
#pragma unroll
        for (int mt = 0; mt < 4; mt++) {
            int row = wm * 64 + mt * 16 + l15;
            LDSM_X4(ah[mt][0], ah[mt][1], ah[mt][2], ah[mt][3],
                    sa + a_off(row, half * 2 + l16));
        }
        uint32_t bf[8][2];
        int kk = half * 16 + l15;
#pragma unroll
        for (int ng = 0; ng < 4; ng++) {
            uint32_t off = b_off(kk, wn * 8 + ng * 2 + l16);
            LDSM_X4T(bf[2 * ng][0], bf[2 * ng][1],
                     bf[2 * ng + 1][0], bf[2 * ng + 1][1], sbB + off);
        }
#pragma unroll
        for (int mt = 0; mt < 4; mt++)
#pragma unroll
            for (int nt = 0; nt < 8; nt++)
                mma_f16(acc[mt][nt], ah[mt], bf[nt][0], bf[nt][1]);
    }
}

// ---------------- launch 0: zero output + counters ---------------------------
__global__ void zero_kernel(float* __restrict__ out) {
    size_t i = (size_t)blockIdx.x * blockDim.x + threadIdx.x;
    const size_t tot4 = (size_t)NTOK * DM / 4;
    if (i < tot4) ((float4*)out)[i] = make_float4(0.f, 0.f, 0.f, 0.f);
    if (i < NE) g_cnt[i] = 0;
}

// ---------------- launch 1: gating (one warp / token) ------------------------
__global__ __launch_bounds__(256) void gating_kernel(
    const float* __restrict__ x, const float* __restrict__ gW,
    const float* __restrict__ gb, float* __restrict__ out_topi, int write_topi) {
    int warp = (int)((blockIdx.x * blockDim.x + threadIdx.x) >> 5);
    int lane = threadIdx.x & 31;
    if (warp >= NTOK) return;
    const float* xr = x + (size_t)warp * DM;
    float acc[NE];
#pragma unroll
    for (int e = 0; e < NE; e++) acc[e] = 0.f;
    for (int d = lane; d < DM; d += 32) {
        float xv = xr[d];
        const float4* w4 = (const float4*)(gW + d * NE);
        float4 wa = w4[0], wb = w4[1];
        acc[0] += xv * wa.x; acc[1] += xv * wa.y;
        acc[2] += xv * wa.z; acc[3] += xv * wa.w;
        acc[4] += xv * wb.x; acc[5] += xv * wb.y;
        acc[6] += xv * wb.z; acc[7] += xv * wb.w;
    }
#pragma unroll
    for (int e = 0; e < NE; e++)
#pragma unroll
        for (int o = 16; o > 0; o >>= 1)
            acc[e] += __shfl_xor_sync(0xffffffffu, acc[e], o);
    if (lane == 0) {
        float v0 = -1e30f, v1 = -1e30f; int i0 = 0, i1 = 0;
#pragma unroll
        for (int e = 0; e < NE; e++) {
            float l = acc[e] + gb[e];
            if (l > v0)      { v1 = v0; i1 = i0; v0 = l; i0 = e; }
            else if (l > v1) { v1 = l;  i1 = e; }
        }
        float e1 = expf(v1 - v0);
        float s  = 1.f + e1;
        float w0 = 1.f / s, w1 = e1 / s;
        int p0 = atomicAdd(&g_cnt[i0], 1);
        g_tok[i0 * NTOK + p0] = warp; g_wt[i0 * NTOK + p0] = w0;
        int p1 = atomicAdd(&g_cnt[i1], 1);
        g_tok[i1 * NTOK + p1] = warp; g_wt[i1 * NTOK + p1] = w1;
        if (write_topi) {
            out_topi[warp * 2 + 0] = (float)i0;
            out_topi[warp * 2 + 1] = (float)i1;
        }
    }
}

// ---------------- launch 2: fused prep (weight fp16 convert + gather) --------
__global__ __launch_bounds__(256) void prep_kernel(
    const float* __restrict__ x, const float* __restrict__ W1,
    const float* __restrict__ W2) {
    const size_t n4 = (size_t)NE * DM * DFFN / 4;
    if (blockIdx.y < 2) {                       // weight fp16 convert
        size_t i = (size_t)blockIdx.x * blockDim.x + threadIdx.x;
        if (i >= n4) return;
        const float* src = blockIdx.y ? W2 : W1;
        __half* dh = blockIdx.y ? W2H : W1H;
        float4 v = ((const float4*)src)[i];
        uint2 hh;
        hh.x = pack_h2(v.x, v.y); hh.y = pack_h2(v.z, v.w);
        ((uint2*)dh)[i] = hh;
    } else {                                    // gather routed rows -> fp16
        int e = blockIdx.x >> 12;               // 4096 x-blocks per expert
        int cnt = g_cnt[e], off = expert_off(e);
        int rbase = (blockIdx.x & 4095) * 4;
#pragma unroll
        for (int rr = 0; rr < 4; rr++) {
            int r = rbase + rr;
            if (r >= cnt) continue;
            int tok = g_tok[e * NTOK + r];
            float4 v = ((const float4*)(x + (size_t)tok * DM))[threadIdx.x];
            uint2 hh;
            hh.x = pack_h2(v.x, v.y); hh.y = pack_h2(v.z, v.w);
            ((uint2*)(XGH + (size_t)(off + r) * DM))[threadIdx.x] = hh;
        }
    }
}

// ---------------- launch 3: GEMM1 (256 thr, 2 CTA/SM, BK=64, 3 stages) -------
__global__ __launch_bounds__(THREADS1, 2) void gemm1_mma(const float* __restrict__ b1) {
    extern __shared__ char smem[];
    int e = blockIdx.z;
    int rows = g_cnt[e], off = expert_off(e);
    int row0 = blockIdx.y * BM;
    if (row0 >= rows) return;
    int n0 = blockIdx.x * BN;
    uint32_t sb = (uint32_t)__cvta_generic_to_shared(smem);
    int tid = threadIdx.x, lane = tid & 31, wid = tid >> 5;
    int wm = wid & 1, wn = wid >> 1;
    const __half* B = W1H + (size_t)e * DM * DFFN;
    size_t arow0 = (size_t)off + row0;

    float acc[4][4][4];
#pragma unroll
    for (int a = 0; a < 4; a++)
#pragma unroll
        for (int b = 0; b < 4; b++)
#pragma unroll
            for (int c = 0; c < 4; c++) acc[a][b][c] = 0.f;

    const int nk = DM / BK;  // 16
#pragma unroll
    for (int p = 0; p < STAGES - 1; p++) {
        load_stage<THREADS1>(sb, p, XGH, DM, B, DFFN, arow0, p * BK, n0, tid);
        CP_COMMIT();
    }
    for (int t = 0; t < nk; t++) {
        CP_WAIT(STAGES - 2);
        __syncthreads();
        int nx = t + STAGES - 1;
        if (nx < nk)
            load_stage<THREADS1>(sb, nx % STAGES, XGH, DM, B, DFFN,
                                 arow0, nx * BK, n0, tid);
        CP_COMMIT();
        compute_stage_a(sb, t % STAGES, acc, wm, wn, lane);
    }

    const float* bias = b1 + (size_t)e * DFFN;
    int quad = lane >> 2, pair = lane & 3;
#pragma unroll
    for (int mt = 0; mt < 4; mt++) {
        int rb = row0 + wm * 64 + mt * 16 + quad;
#pragma unroll
        for (int nt = 0; nt < 4; nt++) {
            int col = n0 + wn * 32 + nt * 8 + pair * 2;
            float bs0 = __ldg(&bias[col]), bs1 = __ldg(&bias[col + 1]);
            if (rb < rows) {
                size_t o = (size_t)(off + rb) * DFFN + col;
                *(uint32_t*)(HH + o) =
                    pack_h2(gelu_f(acc[mt][nt][0] + bs0), gelu_f(acc[mt][nt][1] + bs1));
            }
            if (rb + 8 < rows) {
                size_t o = (size_t)(off + rb + 8) * DFFN + col;
                *(uint32_t*)(HH + o) =
                    pack_h2(gelu_f(acc[mt][nt][2] + bs0), gelu_f(acc[mt][nt][3] + bs1));
            }
        }
    }
}

// ---------------- launch 4: GEMM2 (128 thr, 64x64 warps, BK=64, 3 stages) ----
__global__ __launch_bounds__(THREADS2, 2) void gemm2_mma(
    const float* __restrict__ b2, float* __restrict__ out) {
    extern __shared__ char smem[];
    int e = blockIdx.z;
    int rows = g_cnt[e], off = expert_off(e);
    int row0 = blockIdx.y * BM;
    if (row0 >= rows) return;
    int n0 = blockIdx.x * BN;
    uint32_t sb = (uint32_t)__cvta_generic_to_shared(smem);
    int tid = threadIdx.x, lane = tid & 31, wid = tid >> 5;
    int wm = wid & 1, wn = wid >> 1;
    const __half* B = W2H + (size_t)e * DFFN * DM;
    size_t arow0 = (size_t)off + row0;

    float acc[4][8][4];
#pragma unroll
    for (int a = 0; a < 4; a++)
#pragma unroll
        for (int b = 0; b < 8; b++)
#pragma unroll
            for (int c = 0; c < 4; c++) acc[a][b][c] = 0.f;

    const int nk = DFFN / BK;  // 64
#pragma unroll
    for (int p = 0; p < STAGES - 1; p++) {
        load_stage<THREADS2>(sb, p, HH, DFFN, B, DM, arow0, p * BK, n0, tid);
        CP_COMMIT();
    }
    for (int t = 0; t < nk; t++) {
        CP_WAIT(STAGES - 2);
        __syncthreads();
        int nx = t + STAGES - 1;
        if (nx < nk)
            load_stage<THREADS2>(sb, nx % STAGES, HH, DFFN, B, DM,
                                 arow0, nx * BK, n0, tid);
        CP_COMMIT();
        compute_stage_b(sb, t % STAGES, acc, wm, wn, lane);
    }

    const float* bias = b2 + (size_t)e * DM;
    int quad = lane >> 2, pair = lane & 3;
#pragma unroll
    for (int mt = 0; mt < 4; mt++) {
        int rb = row0 + wm * 64 + mt * 16 + quad;
        int tok0 = 0, tok1 = 0; float wt0 = 0.f, wt1 = 0.f;
        if (rb < rows)     { tok0 = g_tok[e * NTOK + rb];     wt0 = g_wt[e * NTOK + rb]; }
        if (rb + 8 < rows) { tok1 = g_tok[e * NTOK + rb + 8]; wt1 = g_wt[e * NTOK + rb + 8]; }
#pragma unroll
        for (int nt = 0; nt < 8; nt++) {
            int col = n0 + wn * 64 + nt * 8 + pair * 2;
            float bs0 = __ldg(&bias[col]), bs1 = __ldg(&bias[col + 1]);
            if (rb < rows) {
                float* orow = out + (size_t)tok0 * DM + col;
                red_add_v2(orow, (acc[mt][nt][0] + bs0) * wt0,
                                 (acc[mt][nt][1] + bs1) * wt0);
            }
            if (rb + 8 < rows) {
                float* orow = out + (size_t)tok1 * DM + col;
                red_add_v2(orow, (acc[mt][nt][2] + bs0) * wt1,
                                 (acc[mt][nt][3] + bs1) * wt1);
            }
        }
    }
}

// ---------------- host -------------------------------------------------------
extern "C" void kernel_launch(void* const* d_in, const int* in_sizes, int n_in,
                              void* d_out, int out_size) {
    const float* x  = (const float*)d_in[0];
    const float* gW = (const float*)d_in[1];
    const float* gb = (const float*)d_in[2];
    const float* W1 = (const float*)d_in[3];
    const float* b1 = (const float*)d_in[4];
    const float* W2 = (const float*)d_in[5];
    const float* b2 = (const float*)d_in[6];
    float* out = (float*)d_out;
    int write_topi = (out_size >= NTOK * DM + NTOK * TOPK) ? 1 : 0;

    cudaFuncSetAttribute(gemm1_mma, cudaFuncAttributeMaxDynamicSharedMemorySize, SMEM_SZ);
    cudaFuncSetAttribute(gemm2_mma, cudaFuncAttributeMaxDynamicSharedMemorySize, SMEM_SZ);

    {   // launch 0
        size_t tot4 = (size_t)NTOK * DM / 4;
        zero_kernel<<<(int)((tot4 + 255) / 256), 256>>>(out);
    }
    // launch 1
    gating_kernel<<<(NTOK * 32) / 256, 256>>>(x, gW, gb, out + (size_t)NTOK * DM,
                                              write_topi);
    // launch 2: fused weight-convert (y=0,1) + gather (y=2)
    prep_kernel<<<dim3(32768, 3), 256>>>(x, W1, W2);
    // launch 3 (profiler slot): GEMM1, BK=64 / 3 stages
    gemm1_mma<<<dim3(DFFN / BN, NTOK / BM, NE), THREADS1, SMEM_SZ>>>(b1);
    // launch 4: GEMM2, BK=64 / 3 stages + v2 reductions
    gemm2_mma<<<dim3(DM / BN, NTOK / BM, NE), THREADS2, SMEM_SZ>>>(b2, out);
}

// round 14
// speedup vs baseline: 1.0766x; 1.0526x over previous
#include <cuda_runtime.h>
#include <cuda_fp16.h>
#include <cstdint>
#include <math.h>

#define NTOK 16384
#define DM   1024
#define DFFN 4096
#define NE   8
#define TOPK 2

#define BM 128
#define BN 128
// gemm1: BK=64, 3 stages, 256 thr (warp grid 2x4, tile 64x32)
#define BK1 64
#define STAGES1 3
#define THREADS1 256
// gemm2: BK=32, 4 stages, 128 thr (warp grid 2x2, tile 64x64)
#define BK2 32
#define STAGES2 4
#define THREADS2 128

// ---------------- device scratch (static globals: allocation-free) ----------
__device__ int   g_cnt[NE];
__device__ int   g_tok[NE * NTOK];
__device__ float g_wt [NE * NTOK];

// per-expert strided layouts (slot = e*NTOK + r); pad rows never written -> 0
__device__ __align__(16) __half XGH[((size_t)NE * NTOK + BM) * DM];
__device__ __align__(16) __half HH [((size_t)NE * NTOK + BM) * DFFN];
__device__ __align__(16) __half W1H[(size_t)NE * DM * DFFN];
__device__ __align__(16) __half W2H[(size_t)NE * DFFN * DM];

// ---------------- asm helpers ----------------------------------------------
__device__ __forceinline__ void cp16(uint32_t dst, const void* src) {
    asm volatile("cp.async.cg.shared.global [%0], [%1], 16;" :: "r"(dst), "l"(src));
}
#define CP_COMMIT() asm volatile("cp.async.commit_group;" ::: "memory")
#define CP_WAIT(n)  asm volatile("cp.async.wait_group %0;" :: "n"(n) : "memory")

#define LDSM_X4(r0, r1, r2, r3, addr) \
    asm volatile("ldmatrix.sync.aligned.m8n8.x4.shared.b16 {%0,%1,%2,%3}, [%4];" \
                 : "=r"(r0), "=r"(r1), "=r"(r2), "=r"(r3) : "r"(addr))
#define LDSM_X4T(r0, r1, r2, r3, addr) \
    asm volatile("ldmatrix.sync.aligned.m8n8.x4.trans.shared.b16 {%0,%1,%2,%3}, [%4];" \
                 : "=r"(r0), "=r"(r1), "=r"(r2), "=r"(r3) : "r"(addr))

__device__ __forceinline__ void mma_f16(float* c, const uint32_t* a,
                                        uint32_t b0, uint32_t b1) {
    asm volatile(
        "mma.sync.aligned.m16n8k16.row.col.f32.f16.f16.f32 "
        "{%0,%1,%2,%3}, {%4,%5,%6,%7}, {%8,%9}, {%0,%1,%2,%3};"
        : "+f"(c[0]), "+f"(c[1]), "+f"(c[2]), "+f"(c[3])
        : "r"(a[0]), "r"(a[1]), "r"(a[2]), "r"(a[3]), "r"(b0), "r"(b1));
}

// vector reduction (sm_90+): one instruction adds 2 floats to gmem
__device__ __forceinline__ void red_add_v2(float* addr, float y0, float y1) {
    asm volatile("red.global.add.v2.f32 [%0], {%1, %2};"
                 :: "l"(addr), "f"(y0), "f"(y1) : "memory");
}

// ---------------- smem layouts -----------------------------------------------
// gemm1: stage = A 128x64 (16KB) + B 64x128 (16KB) = 32KB; 3 stages = 96KB/CTA
#define STG1 32768u
#define SA1(s) ((uint32_t)(s) * STG1)
#define SB1(s) ((uint32_t)(s) * STG1 + 16384u)
#define SMEM1  (STAGES1 * 32768)
// gemm2: stage = A 128x32 (8KB) + B 32x128 (8KB) = 16KB; 4 stages = 64KB/CTA
#define STG2 16384u
#define SA2(s) ((uint32_t)(s) * STG2)
#define SB2(s) ((uint32_t)(s) * STG2 + 8192u)
#define SMEM2  (STAGES2 * 16384)

// A swizzles: conflict-free for their row pitches
__device__ __forceinline__ uint32_t a_off128(int row, int ch) {   // pitch 128B
    return (uint32_t)(row * 128 + ((ch ^ (row & 7)) << 4));
}
__device__ __forceinline__ uint32_t a_off64(int row, int ch) {    // pitch 64B
    return (uint32_t)(row * 64 + ((ch ^ ((row >> 1) & 3)) << 4));
}
// B: row pitch 256B (16x16B chunks), swizzle low3 of chunk ^= k&7
__device__ __forceinline__ uint32_t b_off(int k, int ch) {
    return (uint32_t)(k * 256 + (((ch & ~7) | ((ch ^ k) & 7)) << 4));
}

__device__ __forceinline__ float gelu_f(float v) {
    return 0.5f * v * (1.f + erff(v * 0.70710678118654752440f));
}
__device__ __forceinline__ uint32_t pack_h2(float a, float b) {
    __half x = __float2half_rn(a), y = __float2half_rn(b);
    return (uint32_t)__half_as_ushort(x) | ((uint32_t)__half_as_ushort(y) << 16);
}

// ---------------- stage loaders ----------------------------------------------
__device__ __forceinline__ void load_stage1(
    uint32_t sb, int stage, const __half* __restrict__ A, size_t lda,
    const __half* __restrict__ B, size_t ldb,
    size_t arow0, int k0, int n0, int tid) {
#pragma unroll
    for (int i = 0; i < 4; i++) {           // A: 1024 chunks (128 rows x 8)
        int ca = tid + THREADS1 * i;
        int row = ca >> 3, ch = ca & 7;
        size_t gsrc = (arow0 + row) * lda + k0 + ch * 8;
        cp16(sb + SA1(stage) + a_off128(row, ch), A + gsrc);
    }
#pragma unroll
    for (int i = 0; i < 4; i++) {           // B: 1024 chunks (64 k x 16)
        int cb = tid + THREADS1 * i;
        int k = cb >> 4, ch = cb & 15;
        size_t gsrc = (size_t)(k0 + k) * ldb + n0 + ch * 8;
        cp16(sb + SB1(stage) + b_off(k, ch), B + gsrc);
    }
}
__device__ __forceinline__ void load_stage2(
    uint32_t sb, int stage, const __half* __restrict__ A, size_t lda,
    const __half* __restrict__ B, size_t ldb,
    size_t arow0, int k0, int n0, int tid) {
#pragma unroll
    for (int i = 0; i < 4; i++) {           // A: 512 chunks (128 rows x 4)
        int ca = tid + THREADS2 * i;
        int row = ca >> 2, ch = ca & 3;
        size_t gsrc = (arow0 + row) * lda + k0 + ch * 8;
        cp16(sb + SA2(stage) + a_off64(row, ch), A + gsrc);
    }
#pragma unroll
    for (int i = 0; i < 4; i++) {           // B: 512 chunks (32 k x 16)
        int cb = tid + THREADS2 * i;
        int k = cb >> 4, ch = cb & 15;
        size_t gsrc = (size_t)(k0 + k) * ldb + n0 + ch * 8;
        cp16(sb + SB2(stage) + b_off(k, ch), B + gsrc);
    }
}

// ---------------- compute A: 8 warps, grid 2x4, warp tile 64x32, BK=64 ------
__device__ __forceinline__ void compute_stage_a(
    uint32_t sb, int stage, float acc[4][4][4], int wm, int wn, int lane) {
    uint32_t sa = sb + SA1(stage);
    uint32_t sbB = sb + SB1(stage);
    int l15 = lane & 15, l16 = lane >> 4;
#pragma unroll
    for (int half = 0; half < 4; half++) {
        uint32_t ah[4][4];
#pragma unroll
        for (int mt = 0; mt < 4; mt++) {
            int row = wm * 64 + mt * 16 + l15;
            LDSM_X4(ah[mt][0], ah[mt][1], ah[mt][2], ah[mt][3],
                    sa + a_off128(row, half * 2 + l16));
        }
        uint32_t bf[4][2];
        int kk = half * 16 + l15;
#pragma unroll
        for (int ng = 0; ng < 2; ng++) {
            uint32_t off = b_off(kk, wn * 4 + ng * 2 + l16);
            LDSM_X4T(bf[2 * ng][0], bf[2 * ng][1],
                     bf[2 * ng + 1][0], bf[2 * ng + 1][1], sbB + off);
        }
#pragma unroll
        for (int mt = 0; mt < 4; mt++)
#pragma unroll
            for (int nt = 0; nt < 4; nt++)
                mma_f16(acc[mt][nt], ah[mt], bf[nt][0], bf[nt][1]);
    }
}

// ---------------- compute B: 4 warps, grid 2x2, warp tile 64x64, BK=32 ------
__device__ __forceinline__ void compute_stage_b(
    uint32_t sb, int stage, float acc[4][8][4], int wm, int wn, int lane) {
    uint32_t sa = sb + SA2(stage);
    uint32_t sbB = sb + SB2(stage);
    int l15 = lane & 15, l16 = lane >> 4;
#pragma unroll
    for (int half = 0; half < 2; half++) {
        uint32_t ah[4][4];
#pragma unroll
        for (int mt = 0; mt < 4; mt++) {
            int row = wm * 64 + mt * 16 + l15;
            LDSM_X4(ah[mt][0], ah[mt][1], ah[mt][2], ah[mt][3],
                    sa + a_off64(row, half * 2 + l16));
        }
        uint32_t bf[8][2];
        int kk = half * 16 + l15;
#pragma unroll
        for (int ng = 0; ng < 4; ng++) {
            uint32_t off = b_off(kk, wn * 8 + ng * 2 + l16);
            LDSM_X4T(bf[2 * ng][0], bf[2 * ng][1],
                     bf[2 * ng + 1][0], bf[2 * ng + 1][1], sbB + off);
        }
#pragma unroll
        for (int mt = 0; mt < 4; mt++)
#pragma unroll
            for (int nt = 0; nt < 8; nt++)
                mma_f16(acc[mt][nt], ah[mt], bf[nt][0], bf[nt][1]);
    }
}

// ---------------- launch 0: zero output + counters ---------------------------
__global__ void zero_kernel(float* __restrict__ out) {
    size_t i = (size_t)blockIdx.x * blockDim.x + threadIdx.x;
    const size_t tot4 = (size_t)NTOK * DM / 4;
    if (i < tot4) ((float4*)out)[i] = make_float4(0.f, 0.f, 0.f, 0.f);
    if (i < NE) g_cnt[i] = 0;
}

// ---------------- launch 1: gating + fused routed scatter --------------------
__global__ __launch_bounds__(256) void gating_kernel(
    const float* __restrict__ x, const float* __restrict__ gW,
    const float* __restrict__ gb, float* __restrict__ out_topi, int write_topi) {
    int warp = (int)((blockIdx.x * blockDim.x + threadIdx.x) >> 5);
    int lane = threadIdx.x & 31;
    if (warp >= NTOK) return;
    const float* xr = x + (size_t)warp * DM;
    float acc[NE];
#pragma unroll
    for (int e = 0; e < NE; e++) acc[e] = 0.f;
    for (int d = lane; d < DM; d += 32) {
        float xv = xr[d];
        const float4* w4 = (const float4*)(gW + d * NE);
        float4 wa = w4[0], wb = w4[1];
        acc[0] += xv * wa.x; acc[1] += xv * wa.y;
        acc[2] += xv * wa.z; acc[3] += xv * wa.w;
        acc[4] += xv * wb.x; acc[5] += xv * wb.y;
        acc[6] += xv * wb.z; acc[7] += xv * wb.w;
    }
#pragma unroll
    for (int e = 0; e < NE; e++)
#pragma unroll
        for (int o = 16; o > 0; o >>= 1)
            acc[e] += __shfl_xor_sync(0xffffffffu, acc[e], o);
    int i0 = 0, i1 = 0, p0 = 0, p1 = 0;
    if (lane == 0) {
        float v0 = -1e30f, v1 = -1e30f;
#pragma unroll
        for (int e = 0; e < NE; e++) {
            float l = acc[e] + gb[e];
            if (l > v0)      { v1 = v0; i1 = i0; v0 = l; i0 = e; }
            else if (l > v1) { v1 = l;  i1 = e; }
        }
        float e1 = expf(v1 - v0);
        float s  = 1.f + e1;
        float w0 = 1.f / s, w1 = e1 / s;
        p0 = atomicAdd(&g_cnt[i0], 1);
        g_tok[i0 * NTOK + p0] = warp; g_wt[i0 * NTOK + p0] = w0;
        p1 = atomicAdd(&g_cnt[i1], 1);
        g_tok[i1 * NTOK + p1] = warp; g_wt[i1 * NTOK + p1] = w1;
        if (write_topi) {
            out_topi[warp * 2 + 0] = (float)i0;
            out_topi[warp * 2 + 1] = (float)i1;
        }
    }
    // broadcast routing, scatter fp16 row into both expert slots
    i0 = __shfl_sync(0xffffffffu, i0, 0); p0 = __shfl_sync(0xffffffffu, p0, 0);
    i1 = __shfl_sync(0xffffffffu, i1, 0); p1 = __shfl_sync(0xffffffffu, p1, 0);
    uint2* d0 = (uint2*)(XGH + ((size_t)i0 * NTOK + p0) * DM);
    uint2* d1 = (uint2*)(XGH + ((size_t)i1 * NTOK + p1) * DM);
    const float4* x4 = (const float4*)xr;
#pragma unroll
    for (int j = 0; j < DM / 128; j++) {        // 256 float4 over 32 lanes
        int f = lane + 32 * j;
        float4 v = x4[f];
        uint2 hh;
        hh.x = pack_h2(v.x, v.y); hh.y = pack_h2(v.z, v.w);
        d0[f] = hh; d1[f] = hh;
    }
}

// ---------------- launch 2: weight fp16 convert ------------------------------
__global__ __launch_bounds__(256) void prep_kernel(
    const float* __restrict__ W1, const float* __restrict__ W2) {
    const size_t n4 = (size_t)NE * DM * DFFN / 4;
    size_t i = (size_t)blockIdx.x * blockDim.x + threadIdx.x;
    if (i >= n4) return;
    const float* src = blockIdx.y ? W2 : W1;
    __half* dh = blockIdx.y ? W2H : W1H;
    float4 v = ((const float4*)src)[i];
    uint2 hh;
    hh.x = pack_h2(v.x, v.y); hh.y = pack_h2(v.z, v.w);
    ((uint2*)dh)[i] = hh;
}

// ---------------- launch 3: GEMM1 (BK=64, 3 stages, 256 thr) -----------------
__global__ __launch_bounds__(THREADS1, 2) void gemm1_mma(const float* __restrict__ b1) {
    extern __shared__ char smem[];
    int e = blockIdx.z;
    int rows = g_cnt[e];
    int row0 = blockIdx.y * BM;
    if (row0 >= rows) return;
    int n0 = blockIdx.x * BN;
    uint32_t sb = (uint32_t)__cvta_generic_to_shared(smem);
    int tid = threadIdx.x, lane = tid & 31, wid = tid >> 5;
    int wm = wid & 1, wn = wid >> 1;
    const __half* B = W1H + (size_t)e * DM * DFFN;
    size_t arow0 = (size_t)e * NTOK + row0;

    float acc[4][4][4];
#pragma unroll
    for (int a = 0; a < 4; a++)
#pragma unroll
        for (int b = 0; b < 4; b++)
#pragma unroll
            for (int c = 0; c < 4; c++) acc[a][b][c] = 0.f;

    const int nk = DM / BK1;  // 16
#pragma unroll
    for (int p = 0; p < STAGES1 - 1; p++) {
        load_stage1(sb, p, XGH, DM, B, DFFN, arow0, p * BK1, n0, tid);
        CP_COMMIT();
    }
    for (int t = 0; t < nk; t++) {
        CP_WAIT(STAGES1 - 2);
        __syncthreads();
        int nx = t + STAGES1 - 1;
        if (nx < nk)
            load_stage1(sb, nx % STAGES1, XGH, DM, B, DFFN,
                        arow0, nx * BK1, n0, tid);
        CP_COMMIT();
        compute_stage_a(sb, t % STAGES1, acc, wm, wn, lane);
    }

    const float* bias = b1 + (size_t)e * DFFN;
    int quad = lane >> 2, pair = lane & 3;
#pragma unroll
    for (int mt = 0; mt < 4; mt++) {
        int rb = row0 + wm * 64 + mt * 16 + quad;
#pragma unroll
        for (int nt = 0; nt < 4; nt++) {
            int col = n0 + wn * 32 + nt * 8 + pair * 2;
            float bs0 = __ldg(&bias[col]), bs1 = __ldg(&bias[col + 1]);
            if (rb < rows) {
                size_t o = ((size_t)e * NTOK + rb) * DFFN + col;
                *(uint32_t*)(HH + o) =
                    pack_h2(gelu_f(acc[mt][nt][0] + bs0), gelu_f(acc[mt][nt][1] + bs1));
            }
            if (rb + 8 < rows) {
                size_t o = ((size_t)e * NTOK + rb + 8) * DFFN + col;
                *(uint32_t*)(HH + o) =
                    pack_h2(gelu_f(acc[mt][nt][2] + bs0), gelu_f(acc[mt][nt][3] + bs1));
            }
        }
    }
}

// ---------------- launch 4: GEMM2 (BK=32, 4 stages, 128 thr) -----------------
__global__ __launch_bounds__(THREADS2, 2) void gemm2_mma(
    const float* __restrict__ b2, float* __restrict__ out) {
    extern __shared__ char smem[];
    int e = blockIdx.z;
    int rows = g_cnt[e];
    int row0 = blockIdx.y * BM;
    if (row0 >= rows) return;
    int n0 = blockIdx.x * BN;
    uint32_t sb = (uint32_t)__cvta_generic_to_shared(smem);
    int tid = threadIdx.x, lane = tid & 31, wid = tid >> 5;
    int wm = wid & 1, wn = wid >> 1;
    const __half* B = W2H + (size_t)e * DFFN * DM;
    size_t arow0 = (size_t)e * NTOK + row0;

    float acc[4][8][4];
#pragma unroll
    for (int a = 0; a < 4; a++)
#pragma unroll
        for (int b = 0; b < 8; b++)
#pragma unroll
            for (int c = 0; c < 4; c++) acc[a][b][c] = 0.f;

    const int nk = DFFN / BK2;  // 128
#pragma unroll
    for (int p = 0; p < STAGES2 - 1; p++) {
        load_stage2(sb, p, HH, DFFN, B, DM, arow0, p * BK2, n0, tid);
        CP_COMMIT();
    }
    for (int t = 0; t < nk; t++) {
        CP_WAIT(STAGES2 - 2);
        __syncthreads();
        int nx = t + STAGES2 - 1;
        if (nx < nk)
            load_stage2(sb, nx % STAGES2, HH, DFFN, B, DM,
                        arow0, nx * BK2, n0, tid);
        CP_COMMIT();
        compute_stage_b(sb, t % STAGES2, acc, wm, wn, lane);
    }

    const float* bias = b2 + (size_t)e * DM;
    int quad = lane >> 2, pair = lane & 3;
#pragma unroll
    for (int mt = 0; mt < 4; mt++) {
        int rb = row0 + wm * 64 + mt * 16 + quad;
        int tok0 = 0, tok1 = 0; float wt0 = 0.f, wt1 = 0.f;
        if (rb < rows)     { tok0 = g_tok[e * NTOK + rb];     wt0 = g_wt[e * NTOK + rb]; }
        if (rb + 8 < rows) { tok1 = g_tok[e * NTOK + rb + 8]; wt1 = g_wt[e * NTOK + rb + 8]; }
#pragma unroll
        for (int nt = 0; nt < 8; nt++) {
            int col = n0 + wn * 64 + nt * 8 + pair * 2;
            float bs0 = __ldg(&bias[col]), bs1 = __ldg(&bias[col + 1]);
            if (rb < rows) {
                float* orow = out + (size_t)tok0 * DM + col;
                red_add_v2(orow, (acc[mt][nt][0] + bs0) * wt0,
                                 (acc[mt][nt][1] + bs1) * wt0);
            }
            if (rb + 8 < rows) {
                float* orow = out + (size_t)tok1 * DM + col;
                red_add_v2(orow, (acc[mt][nt][2] + bs0) * wt1,
                                 (acc[mt][nt][3] + bs1) * wt1);
            }
        }
    }
}

// ---------------- host -------------------------------------------------------
extern "C" void kernel_launch(void* const* d_in, const int* in_sizes, int n_in,
                              void* d_out, int out_size) {
    const float* x  = (const float*)d_in[0];
    const float* gW = (const float*)d_in[1];
    const float* gb = (const float*)d_in[2];
    const float* W1 = (const float*)d_in[3];
    const float* b1 = (const float*)d_in[4];
    const float* W2 = (const float*)d_in[5];
    const float* b2 = (const float*)d_in[6];
    float* out = (float*)d_out;
    int write_topi = (out_size >= NTOK * DM + NTOK * TOPK) ? 1 : 0;

    cudaFuncSetAttribute(gemm1_mma, cudaFuncAttributeMaxDynamicSharedMemorySize, SMEM1);
    cudaFuncSetAttribute(gemm2_mma, cudaFuncAttributeMaxDynamicSharedMemorySize, SMEM2);

    {   // launch 0
        size_t tot4 = (size_t)NTOK * DM / 4;
        zero_kernel<<<(int)((tot4 + 255) / 256), 256>>>(out);
    }
    // launch 1: gating + fused scatter into per-expert strided XGH
    gating_kernel<<<(NTOK * 32) / 256, 256>>>(x, gW, gb, out + (size_t)NTOK * DM,
                                              write_topi);
    // launch 2: weight fp16 convert only
    prep_kernel<<<dim3(32768, 2), 256>>>(W1, W2);
    // launch 3 (profiler slot): GEMM1, BK=64 / 3 stages
    gemm1_mma<<<dim3(DFFN / BN, NTOK / BM, NE), THREADS1, SMEM1>>>(b1);
    // launch 4: GEMM2, BK=32 / 4 stages + v2 reductions
    gemm2_mma<<<dim3(DM / BN, NTOK / BM, NE), THREADS2, SMEM2>>>(b2, out);
}

// round 15
// speedup vs baseline: 1.0827x; 1.0057x over previous
#include <cuda_runtime.h>
#include <cuda_fp16.h>
#include <cstdint>
#include <math.h>

#define NTOK 16384
#define DM   1024
#define DFFN 4096
#define NE   8
#define TOPK 2

#define BM 128
#define BN 128
// gemm1: BK=64, 3 stages, 256 thr (warp grid 2x4, tile 64x32)
#define BK1 64
#define STAGES1 3
#define THREADS1 256
// gemm2: BK=32, 4 stages, 128 thr (warp grid 2x2, tile 64x64)
#define BK2 32
#define STAGES2 4
#define THREADS2 128

// ---------------- device scratch (static globals: allocation-free) ----------
__device__ int   g_cnt[NE];
__device__ int   g_tok[NE * NTOK];
__device__ float g_wt [NE * NTOK];

// per-expert strided layouts (slot = e*NTOK + r); pad rows never written -> 0
__device__ __align__(16) __half XGH[((size_t)NE * NTOK + BM) * DM];
__device__ __align__(16) __half HH [((size_t)NE * NTOK + BM) * DFFN];
__device__ __align__(16) __half W1H[(size_t)NE * DM * DFFN];
__device__ __align__(16) __half W2H[(size_t)NE * DFFN * DM];

// ---------------- asm helpers ----------------------------------------------
__device__ __forceinline__ void cp16(uint32_t dst, const void* src) {
    asm volatile("cp.async.cg.shared.global [%0], [%1], 16;" :: "r"(dst), "l"(src));
}
#define CP_COMMIT() asm volatile("cp.async.commit_group;" ::: "memory")
#define CP_WAIT(n)  asm volatile("cp.async.wait_group %0;" :: "n"(n) : "memory")

#define LDSM_X4(r0, r1, r2, r3, addr) \
    asm volatile("ldmatrix.sync.aligned.m8n8.x4.shared.b16 {%0,%1,%2,%3}, [%4];" \
                 : "=r"(r0), "=r"(r1), "=r"(r2), "=r"(r3) : "r"(addr))
#define LDSM_X4T(r0, r1, r2, r3, addr) \
    asm volatile("ldmatrix.sync.aligned.m8n8.x4.trans.shared.b16 {%0,%1,%2,%3}, [%4];" \
                 : "=r"(r0), "=r"(r1), "=r"(r2), "=r"(r3) : "r"(addr))

__device__ __forceinline__ void mma_f16(float* c, const uint32_t* a,
                                        uint32_t b0, uint32_t b1) {
    asm volatile(
        "mma.sync.aligned.m16n8k16.row.col.f32.f16.f16.f32 "
        "{%0,%1,%2,%3}, {%4,%5,%6,%7}, {%8,%9}, {%0,%1,%2,%3};"
        : "+f"(c[0]), "+f"(c[1]), "+f"(c[2]), "+f"(c[3])
        : "r"(a[0]), "r"(a[1]), "r"(a[2]), "r"(a[3]), "r"(b0), "r"(b1));
}

// vector reduction (sm_90+): one instruction adds 2 floats to gmem
__device__ __forceinline__ void red_add_v2(float* addr, float y0, float y1) {
    asm volatile("red.global.add.v2.f32 [%0], {%1, %2};"
                 :: "l"(addr), "f"(y0), "f"(y1) : "memory");
}

// ---------------- smem layouts -----------------------------------------------
#define STG1 32768u
#define SA1(s) ((uint32_t)(s) * STG1)
#define SB1(s) ((uint32_t)(s) * STG1 + 16384u)
#define SMEM1  (STAGES1 * 32768)
#define STG2 16384u
#define SA2(s) ((uint32_t)(s) * STG2)
#define SB2(s) ((uint32_t)(s) * STG2 + 8192u)
#define SMEM2  (STAGES2 * 16384)

// A swizzles: conflict-free for their row pitches
__device__ __forceinline__ uint32_t a_off128(int row, int ch) {   // pitch 128B
    return (uint32_t)(row * 128 + ((ch ^ (row & 7)) << 4));
}
__device__ __forceinline__ uint32_t a_off64(int row, int ch) {    // pitch 64B
    return (uint32_t)(row * 64 + ((ch ^ ((row >> 1) & 3)) << 4));
}
// B: row pitch 256B (16x16B chunks), swizzle low3 of chunk ^= k&7
__device__ __forceinline__ uint32_t b_off(int k, int ch) {
    return (uint32_t)(k * 256 + (((ch & ~7) | ((ch ^ k) & 7)) << 4));
}

__device__ __forceinline__ float gelu_f(float v) {
    return 0.5f * v * (1.f + erff(v * 0.70710678118654752440f));
}
__device__ __forceinline__ uint32_t pack_h2(float a, float b) {
    __half x = __float2half_rn(a), y = __float2half_rn(b);
    return (uint32_t)__half_as_ushort(x) | ((uint32_t)__half_as_ushort(y) << 16);
}

// ---------------- stage loaders ----------------------------------------------
__device__ __forceinline__ void load_stage1(
    uint32_t sb, int stage, const __half* __restrict__ A, size_t lda,
    const __half* __restrict__ B, size_t ldb,
    size_t arow0, int k0, int n0, int tid) {
#pragma unroll
    for (int i = 0; i < 4; i++) {           // A: 1024 chunks (128 rows x 8)
        int ca = tid + THREADS1 * i;
        int row = ca >> 3, ch = ca & 7;
        size_t gsrc = (arow0 + row) * lda + k0 + ch * 8;
        cp16(sb + SA1(stage) + a_off128(row, ch), A + gsrc);
    }
#pragma unroll
    for (int i = 0; i < 4; i++) {           // B: 1024 chunks (64 k x 16)
        int cb = tid + THREADS1 * i;
        int k = cb >> 4, ch = cb & 15;
        size_t gsrc = (size_t)(k0 + k) * ldb + n0 + ch * 8;
        cp16(sb + SB1(stage) + b_off(k, ch), B + gsrc);
    }
}
__device__ __forceinline__ void load_stage2(
    uint32_t sb, int stage, const __half* __restrict__ A, size_t lda,
    const __half* __restrict__ B, size_t ldb,
    size_t arow0, int k0, int n0, int tid) {
#pragma unroll
    for (int i = 0; i < 4; i++) {           // A: 512 chunks (128 rows x 4)
        int ca = tid + THREADS2 * i;
        int row = ca >> 2, ch = ca & 3;
        size_t gsrc = (arow0 + row) * lda + k0 + ch * 8;
        cp16(sb + SA2(stage) + a_off64(row, ch), A + gsrc);
    }
#pragma unroll
    for (int i = 0; i < 4; i++) {           // B: 512 chunks (32 k x 16)
        int cb = tid + THREADS2 * i;
        int k = cb >> 4, ch = cb & 15;
        size_t gsrc = (size_t)(k0 + k) * ldb + n0 + ch * 8;
        cp16(sb + SB2(stage) + b_off(k, ch), B + gsrc);
    }
}

// ---------------- compute A: 8 warps, grid 2x4, warp tile 64x32, BK=64 ------
__device__ __forceinline__ void compute_stage_a(
    uint32_t sb, int stage, float acc[4][4][4], int wm, int wn, int lane) {
    uint32_t sa = sb + SA1(stage);
    uint32_t sbB = sb + SB1(stage);
    int l15 = lane & 15, l16 = lane >> 4;
#pragma unroll
    for (int half = 0; half < 4; half++) {
        uint32_t ah[4][4];
#pragma unroll
        for (int mt = 0; mt < 4; mt++) {
            int row = wm * 64 + mt * 16 + l15;
            LDSM_X4(ah[mt][0], ah[mt][1], ah[mt][2], ah[mt][3],
                    sa + a_off128(row, half * 2 + l16));
        }
        uint32_t bf[4][2];
        int kk = half * 16 + l15;
#pragma unroll
        for (int ng = 0; ng < 2; ng++) {
            uint32_t off = b_off(kk, wn * 4 + ng * 2 + l16);
            LDSM_X4T(bf[2 * ng][0], bf[2 * ng][1],
                     bf[2 * ng + 1][0], bf[2 * ng + 1][1], sbB + off);
        }
#pragma unroll
        for (int mt = 0; mt < 4; mt++)
#pragma unroll
            for (int nt = 0; nt < 4; nt++)
                mma_f16(acc[mt][nt], ah[mt], bf[nt][0], bf[nt][1]);
    }
}

// ---------------- compute B: 4 warps, grid 2x2, warp tile 64x64, BK=32 ------
__device__ __forceinline__ void compute_stage_b(
    uint32_t sb, int stage, float acc[4][8][4], int wm, int wn, int lane) {
    uint32_t sa = sb + SA2(stage);
    uint32_t sbB = sb + SB2(stage);
    int l15 = lane & 15, l16 = lane >> 4;
#pragma unroll
    for (int half = 0; half < 2; half++) {
        uint32_t ah[4][4];
#pragma unroll
        for (int mt = 0; mt < 4; mt++) {
            int row = wm * 64 + mt * 16 + l15;
            LDSM_X4(ah[mt][0], ah[mt][1], ah[mt][2], ah[mt][3],
                    sa + a_off64(row, half * 2 + l16));
        }
        uint32_t bf[8][2];
        int kk = half * 16 + l15;
#pragma unroll
        for (int ng = 0; ng < 4; ng++) {
            uint32_t off = b_off(kk, wn * 8 + ng * 2 + l16);
            LDSM_X4T(bf[2 * ng][0], bf[2 * ng][1],
                     bf[2 * ng + 1][0], bf[2 * ng + 1][1], sbB + off);
        }
#pragma unroll
        for (int mt = 0; mt < 4; mt++)
#pragma unroll
            for (int nt = 0; nt < 8; nt++)
                mma_f16(acc[mt][nt], ah[mt], bf[nt][0], bf[nt][1]);
    }
}

// ---------------- launch 0: init counters (must precede gating atomics) ------
__global__ void init_kernel() {
    if (threadIdx.x < NE) g_cnt[threadIdx.x] = 0;
}

// ---------------- launch 1: fused prologue -----------------------------------
// blocks [0, 2048):          gating + routed fp16 scatter  (8 warps/block)
// blocks [2048, 18432):      zero out (16384 blocks x 1024 floats)
// blocks [18432, 51200):     W1 fp32 -> fp16 convert
// blocks [51200, 83968):     W2 fp32 -> fp16 convert
#define GATE_BLOCKS 2048
#define ZERO_BLOCKS 16384
#define CONV_BLOCKS 32768
#define FUSED_BLOCKS (GATE_BLOCKS + ZERO_BLOCKS + 2 * CONV_BLOCKS)

__global__ __launch_bounds__(256) void fused_prep_kernel(
    const float* __restrict__ x, const float* __restrict__ gW,
    const float* __restrict__ gb, const float* __restrict__ W1,
    const float* __restrict__ W2, float* __restrict__ out, int write_topi) {
    int blk = blockIdx.x;
    if (blk < GATE_BLOCKS) {
        // ---- gating: one warp per token ----
        int warp = blk * 8 + (threadIdx.x >> 5);
        int lane = threadIdx.x & 31;
        const float* xr = x + (size_t)warp * DM;
        float acc[NE];
#pragma unroll
        for (int e = 0; e < NE; e++) acc[e] = 0.f;
        for (int d = lane; d < DM; d += 32) {
            float xv = xr[d];
            const float4* w4 = (const float4*)(gW + d * NE);
            float4 wa = w4[0], wb = w4[1];
            acc[0] += xv * wa.x; acc[1] += xv * wa.y;
            acc[2] += xv * wa.z; acc[3] += xv * wa.w;
            acc[4] += xv * wb.x; acc[5] += xv * wb.y;
            acc[6] += xv * wb.z; acc[7] += xv * wb.w;
        }
#pragma unroll
        for (int e = 0; e < NE; e++)
#pragma unroll
            for (int o = 16; o > 0; o >>= 1)
                acc[e] += __shfl_xor_sync(0xffffffffu, acc[e], o);
        int i0 = 0, i1 = 0, p0 = 0, p1 = 0;
        if (lane == 0) {
            float v0 = -1e30f, v1 = -1e30f;
#pragma unroll
            for (int e = 0; e < NE; e++) {
                float l = acc[e] + gb[e];
                if (l > v0)      { v1 = v0; i1 = i0; v0 = l; i0 = e; }
                else if (l > v1) { v1 = l;  i1 = e; }
            }
            float e1 = expf(v1 - v0);
            float s  = 1.f + e1;
            float w0 = 1.f / s, w1 = e1 / s;
            p0 = atomicAdd(&g_cnt[i0], 1);
            g_tok[i0 * NTOK + p0] = warp; g_wt[i0 * NTOK + p0] = w0;
            p1 = atomicAdd(&g_cnt[i1], 1);
            g_tok[i1 * NTOK + p1] = warp; g_wt[i1 * NTOK + p1] = w1;
            if (write_topi) {
                out[(size_t)NTOK * DM + warp * 2 + 0] = (float)i0;
                out[(size_t)NTOK * DM + warp * 2 + 1] = (float)i1;
            }
        }
        i0 = __shfl_sync(0xffffffffu, i0, 0); p0 = __shfl_sync(0xffffffffu, p0, 0);
        i1 = __shfl_sync(0xffffffffu, i1, 0); p1 = __shfl_sync(0xffffffffu, p1, 0);
        uint2* d0 = (uint2*)(XGH + ((size_t)i0 * NTOK + p0) * DM);
        uint2* d1 = (uint2*)(XGH + ((size_t)i1 * NTOK + p1) * DM);
        const float4* x4 = (const float4*)xr;
#pragma unroll
        for (int j = 0; j < DM / 128; j++) {
            int f = lane + 32 * j;
            float4 v = x4[f];
            uint2 hh;
            hh.x = pack_h2(v.x, v.y); hh.y = pack_h2(v.z, v.w);
            d0[f] = hh; d1[f] = hh;
        }
    } else if (blk < GATE_BLOCKS + ZERO_BLOCKS) {
        // ---- zero out[NTOK*DM] ----
        size_t i = (size_t)(blk - GATE_BLOCKS) * 256 + threadIdx.x;
        ((float4*)out)[i] = make_float4(0.f, 0.f, 0.f, 0.f);
    } else {
        // ---- weight fp32 -> fp16 convert ----
        int cblk = blk - GATE_BLOCKS - ZERO_BLOCKS;
        const float* src = (cblk < CONV_BLOCKS) ? W1 : W2;
        __half* dh = (cblk < CONV_BLOCKS) ? W1H : W2H;
        size_t i = (size_t)(cblk % CONV_BLOCKS) * 256 + threadIdx.x;
        float4 v = ((const float4*)src)[i];
        uint2 hh;
        hh.x = pack_h2(v.x, v.y); hh.y = pack_h2(v.z, v.w);
        ((uint2*)dh)[i] = hh;
    }
}

// ---------------- launch 2: GEMM1 (BK=64, 3 stages, 256 thr) -----------------
__global__ __launch_bounds__(THREADS1, 2) void gemm1_mma(const float* __restrict__ b1) {
    extern __shared__ char smem[];
    int e = blockIdx.z;
    int rows = g_cnt[e];
    int row0 = blockIdx.y * BM;
    if (row0 >= rows) return;
    int n0 = blockIdx.x * BN;
    uint32_t sb = (uint32_t)__cvta_generic_to_shared(smem);
    int tid = threadIdx.x, lane = tid & 31, wid = tid >> 5;
    int wm = wid & 1, wn = wid >> 1;
    const __half* B = W1H + (size_t)e * DM * DFFN;
    size_t arow0 = (size_t)e * NTOK + row0;

    float acc[4][4][4];
#pragma unroll
    for (int a = 0; a < 4; a++)
#pragma unroll
        for (int b = 0; b < 4; b++)
#pragma unroll
            for (int c = 0; c < 4; c++) acc[a][b][c] = 0.f;

    const int nk = DM / BK1;  // 16
#pragma unroll
    for (int p = 0; p < STAGES1 - 1; p++) {
        load_stage1(sb, p, XGH, DM, B, DFFN, arow0, p * BK1, n0, tid);
        CP_COMMIT();
    }
    for (int t = 0; t < nk; t++) {
        CP_WAIT(STAGES1 - 2);
        __syncthreads();
        int nx = t + STAGES1 - 1;
        if (nx < nk)
            load_stage1(sb, nx % STAGES1, XGH, DM, B, DFFN,
                        arow0, nx * BK1, n0, tid);
        CP_COMMIT();
        compute_stage_a(sb, t % STAGES1, acc, wm, wn, lane);
    }

    const float* bias = b1 + (size_t)e * DFFN;
    int quad = lane >> 2, pair = lane & 3;
#pragma unroll
    for (int mt = 0; mt < 4; mt++) {
        int rb = row0 + wm * 64 + mt * 16 + quad;
#pragma unroll
        for (int nt = 0; nt < 4; nt++) {
            int col = n0 + wn * 32 + nt * 8 + pair * 2;
            float bs0 = __ldg(&bias[col]), bs1 = __ldg(&bias[col + 1]);
            if (rb < rows) {
                size_t o = ((size_t)e * NTOK + rb) * DFFN + col;
                *(uint32_t*)(HH + o) =
                    pack_h2(gelu_f(acc[mt][nt][0] + bs0), gelu_f(acc[mt][nt][1] + bs1));
            }
            if (rb + 8 < rows) {
                size_t o = ((size_t)e * NTOK + rb + 8) * DFFN + col;
                *(uint32_t*)(HH + o) =
                    pack_h2(gelu_f(acc[mt][nt][2] + bs0), gelu_f(acc[mt][nt][3] + bs1));
            }
        }
    }
}

// ---------------- launch 3: GEMM2 (BK=32, 4 stages, 128 thr) -----------------
__global__ __launch_bounds__(THREADS2, 2) void gemm2_mma(
    const float* __restrict__ b2, float* __restrict__ out) {
    extern __shared__ char smem[];
    int e = blockIdx.z;
    int rows = g_cnt[e];
    int row0 = blockIdx.y * BM;
    if (row0 >= rows) return;
    int n0 = blockIdx.x * BN;
    uint32_t sb = (uint32_t)__cvta_generic_to_shared(smem);
    int tid = threadIdx.x, lane = tid & 31, wid = tid >> 5;
    int wm = wid & 1, wn = wid >> 1;
    const __half* B = W2H + (size_t)e * DFFN * DM;
    size_t arow0 = (size_t)e * NTOK + row0;

    float acc[4][8][4];
#pragma unroll
    for (int a = 0; a < 4; a++)
#pragma unroll
        for (int b = 0; b < 8; b++)
#pragma unroll
            for (int c = 0; c < 4; c++) acc[a][b][c] = 0.f;

    const int nk = DFFN / BK2;  // 128
#pragma unroll
    for (int p = 0; p < STAGES2 - 1; p++) {
        load_stage2(sb, p, HH, DFFN, B, DM, arow0, p * BK2, n0, tid);
        CP_COMMIT();
    }
    for (int t = 0; t < nk; t++) {
        CP_WAIT(STAGES2 - 2);
        __syncthreads();
        int nx = t + STAGES2 - 1;
        if (nx < nk)
            load_stage2(sb, nx % STAGES2, HH, DFFN, B, DM,
                        arow0, nx * BK2, n0, tid);
        CP_COMMIT();
        compute_stage_b(sb, t % STAGES2, acc, wm, wn, lane);
    }

    const float* bias = b2 + (size_t)e * DM;
    int quad = lane >> 2, pair = lane & 3;
#pragma unroll
    for (int mt = 0; mt < 4; mt++) {
        int rb = row0 + wm * 64 + mt * 16 + quad;
        int tok0 = 0, tok1 = 0; float wt0 = 0.f, wt1 = 0.f;
        if (rb < rows)     { tok0 = g_tok[e * NTOK + rb];     wt0 = g_wt[e * NTOK + rb]; }
        if (rb + 8 < rows) { tok1 = g_tok[e * NTOK + rb + 8]; wt1 = g_wt[e * NTOK + rb + 8]; }
#pragma unroll
        for (int nt = 0; nt < 8; nt++) {
            int col = n0 + wn * 64 + nt * 8 + pair * 2;
            float bs0 = __ldg(&bias[col]), bs1 = __ldg(&bias[col + 1]);
            if (rb < rows) {
                float* orow = out + (size_t)tok0 * DM + col;
                red_add_v2(orow, (acc[mt][nt][0] + bs0) * wt0,
                                 (acc[mt][nt][1] + bs1) * wt0);
            }
            if (rb + 8 < rows) {
                float* orow = out + (size_t)tok1 * DM + col;
                red_add_v2(orow, (acc[mt][nt][2] + bs0) * wt1,
                                 (acc[mt][nt][3] + bs1) * wt1);
            }
        }
    }
}

// ---------------- host -------------------------------------------------------
extern "C" void kernel_launch(void* const* d_in, const int* in_sizes, int n_in,
                              void* d_out, int out_size) {
    const float* x  = (const float*)d_in[0];
    const float* gW = (const float*)d_in[1];
    const float* gb = (const float*)d_in[2];
    const float* W1 = (const float*)d_in[3];
    const float* b1 = (const float*)d_in[4];
    const float* W2 = (const float*)d_in[5];
    const float* b2 = (const float*)d_in[6];
    float* out = (float*)d_out;
    int write_topi = (out_size >= NTOK * DM + NTOK * TOPK) ? 1 : 0;

    cudaFuncSetAttribute(gemm1_mma, cudaFuncAttributeMaxDynamicSharedMemorySize, SMEM1);
    cudaFuncSetAttribute(gemm2_mma, cudaFuncAttributeMaxDynamicSharedMemorySize, SMEM2);

    // launch 0: counter init only (tiny)
    init_kernel<<<1, 32>>>();
    // launch 1: fused gating+scatter / out-zero / weight-convert
    fused_prep_kernel<<<FUSED_BLOCKS, 256>>>(x, gW, gb, W1, W2, out, write_topi);
    // launch 2: GEMM1, BK=64 / 3 stages
    gemm1_mma<<<dim3(DFFN / BN, NTOK / BM, NE), THREADS1, SMEM1>>>(b1);
    // launch 3: GEMM2, BK=32 / 4 stages + v2 reductions
    gemm2_mma<<<dim3(DM / BN, NTOK / BM, NE), THREADS2, SMEM2>>>(b2, out);
}

// round 16
// speedup vs baseline: 1.1571x; 1.0687x over previous
#include <cuda_runtime.h>
#include <cuda_fp16.h>
#include <cstdint>
#include <math.h>

#define NTOK 16384
#define DM   1024
#define DFFN 4096
#define NE   8
#define TOPK 2

#define BM 128
#define BN 128
// gemm1: BK=64, 3 stages, 256 thr (warp grid 2x4, tile 64x32)
#define BK1 64
#define STAGES1 3
#define THREADS1 256
// gemm2: BK=32, 4 stages, 128 thr (warp grid 2x2, tile 64x64)
#define BK2 32
#define STAGES2 4
#define THREADS2 128

// ---------------- device scratch (static globals: allocation-free) ----------
__device__ int   g_cnt[NE];
__device__ int   g_tok[NE * NTOK];
__device__ float g_wt [NE * NTOK];

// per-expert strided layouts (slot = e*NTOK + r); pad rows never written -> 0
__device__ __align__(16) __half XGH[((size_t)NE * NTOK + BM) * DM];
__device__ __align__(16) __half HH [((size_t)NE * NTOK + BM) * DFFN];
__device__ __align__(16) __half W1H[(size_t)NE * DM * DFFN];
__device__ __align__(16) __half W2H[(size_t)NE * DFFN * DM];

// ---------------- asm helpers ----------------------------------------------
__device__ __forceinline__ void cp16(uint32_t dst, const void* src) {
    asm volatile("cp.async.cg.shared.global [%0], [%1], 16;" :: "r"(dst), "l"(src));
}
#define CP_COMMIT() asm volatile("cp.async.commit_group;" ::: "memory")
#define CP_WAIT(n)  asm volatile("cp.async.wait_group %0;" :: "n"(n) : "memory")

#define LDSM_X4(r0, r1, r2, r3, addr) \
    asm volatile("ldmatrix.sync.aligned.m8n8.x4.shared.b16 {%0,%1,%2,%3}, [%4];" \
                 : "=r"(r0), "=r"(r1), "=r"(r2), "=r"(r3) : "r"(addr))
#define LDSM_X4T(r0, r1, r2, r3, addr) \
    asm volatile("ldmatrix.sync.aligned.m8n8.x4.trans.shared.b16 {%0,%1,%2,%3}, [%4];" \
                 : "=r"(r0), "=r"(r1), "=r"(r2), "=r"(r3) : "r"(addr))

__device__ __forceinline__ void mma_f16(float* c, const uint32_t* a,
                                        uint32_t b0, uint32_t b1) {
    asm volatile(
        "mma.sync.aligned.m16n8k16.row.col.f32.f16.f16.f32 "
        "{%0,%1,%2,%3}, {%4,%5,%6,%7}, {%8,%9}, {%0,%1,%2,%3};"
        : "+f"(c[0]), "+f"(c[1]), "+f"(c[2]), "+f"(c[3])
        : "r"(a[0]), "r"(a[1]), "r"(a[2]), "r"(a[3]), "r"(b0), "r"(b1));
}

// vector reduction (sm_90+): one instruction adds 2 floats to gmem
__device__ __forceinline__ void red_add_v2(float* addr, float y0, float y1) {
    asm volatile("red.global.add.v2.f32 [%0], {%1, %2};"
                 :: "l"(addr), "f"(y0), "f"(y1) : "memory");
}

// ---------------- smem layouts -----------------------------------------------
#define STG1 32768u
#define SA1(s) ((uint32_t)(s) * STG1)
#define SB1(s) ((uint32_t)(s) * STG1 + 16384u)
#define SMEM1  (STAGES1 * 32768)
#define STG2 16384u
#define SA2(s) ((uint32_t)(s) * STG2)
#define SB2(s) ((uint32_t)(s) * STG2 + 8192u)
#define SMEM2  (STAGES2 * 16384)

// A swizzles: conflict-free for their row pitches
__device__ __forceinline__ uint32_t a_off128(int row, int ch) {   // pitch 128B
    return (uint32_t)(row * 128 + ((ch ^ (row & 7)) << 4));
}
__device__ __forceinline__ uint32_t a_off64(int row, int ch) {    // pitch 64B
    return (uint32_t)(row * 64 + ((ch ^ ((row >> 1) & 3)) << 4));
}
// B: row pitch 256B (16x16B chunks), swizzle low3 of chunk ^= k&7
__device__ __forceinline__ uint32_t b_off(int k, int ch) {
    return (uint32_t)(k * 256 + (((ch & ~7) | ((ch ^ k) & 7)) << 4));
}

__device__ __forceinline__ float gelu_f(float v) {
    return 0.5f * v * (1.f + erff(v * 0.70710678118654752440f));
}
__device__ __forceinline__ uint32_t pack_h2(float a, float b) {
    __half x = __float2half_rn(a), y = __float2half_rn(b);
    return (uint32_t)__half_as_ushort(x) | ((uint32_t)__half_as_ushort(y) << 16);
}

// ---------------- stage loaders ----------------------------------------------
__device__ __forceinline__ void load_stage1(
    uint32_t sb, int stage, const __half* __restrict__ A, size_t lda,
    const __half* __restrict__ B, size_t ldb,
    size_t arow0, int k0, int n0, int tid) {
#pragma unroll
    for (int i = 0; i < 4; i++) {           // A: 1024 chunks (128 rows x 8)
        int ca = tid + THREADS1 * i;
        int row = ca >> 3, ch = ca & 7;
        size_t gsrc = (arow0 + row) * lda + k0 + ch * 8;
        cp16(sb + SA1(stage) + a_off128(row, ch), A + gsrc);
    }
#pragma unroll
    for (int i = 0; i < 4; i++) {           // B: 1024 chunks (64 k x 16)
        int cb = tid + THREADS1 * i;
        int k = cb >> 4, ch = cb & 15;
        size_t gsrc = (size_t)(k0 + k) * ldb + n0 + ch * 8;
        cp16(sb + SB1(stage) + b_off(k, ch), B + gsrc);
    }
}
__device__ __forceinline__ void load_stage2(
    uint32_t sb, int stage, const __half* __restrict__ A, size_t lda,
    const __half* __restrict__ B, size_t ldb,
    size_t arow0, int k0, int n0, int tid) {
#pragma unroll
    for (int i = 0; i < 4; i++) {           // A: 512 chunks (128 rows x 4)
        int ca = tid + THREADS2 * i;
        int row = ca >> 2, ch = ca & 3;
        size_t gsrc = (arow0 + row) * lda + k0 + ch * 8;
        cp16(sb + SA2(stage) + a_off64(row, ch), A + gsrc);
    }
#pragma unroll
    for (int i = 0; i < 4; i++) {           // B: 512 chunks (32 k x 16)
        int cb = tid + THREADS2 * i;
        int k = cb >> 4, ch = cb & 15;
        size_t gsrc = (size_t)(k0 + k) * ldb + n0 + ch * 8;
        cp16(sb + SB2(stage) + b_off(k, ch), B + gsrc);
    }
}

// ---------------- compute A: 8 warps, grid 2x4, warp tile 64x32, BK=64 ------
__device__ __forceinline__ void compute_stage_a(
    uint32_t sb, int stage, float acc[4][4][4], int wm, int wn, int lane) {
    uint32_t sa = sb + SA1(stage);
    uint32_t sbB = sb + SB1(stage);
    int l15 = lane & 15, l16 = lane >> 4;
#pragma unroll
    for (int half = 0; half < 4; half++) {
        uint32_t ah[4][4];
#pragma unroll
        for (int mt = 0; mt < 4; mt++) {
            int row = wm * 64 + mt * 16 + l15;
            LDSM_X4(ah[mt][0], ah[mt][1], ah[mt][2], ah[mt][3],
                    sa + a_off128(row, half * 2 + l16));
        }
        uint32_t bf[4][2];
        int kk = half * 16 + l15;
#pragma unroll
        for (int ng = 0; ng < 2; ng++) {
            uint32_t off = b_off(kk, wn * 4 + ng * 2 + l16);
            LDSM_X4T(bf[2 * ng][0], bf[2 * ng][1],
                     bf[2 * ng + 1][0], bf[2 * ng + 1][1], sbB + off);
        }
#pragma unroll
        for (int mt = 0; mt < 4; mt++)
#pragma unroll
            for (int nt = 0; nt < 4; nt++)
                mma_f16(acc[mt][nt], ah[mt], bf[nt][0], bf[nt][1]);
    }
}

// ---------------- compute B: 4 warps, grid 2x2, warp tile 64x64, BK=32 ------
__device__ __forceinline__ void compute_stage_b(
    uint32_t sb, int stage, float acc[4][8][4], int wm, int wn, int lane) {
    uint32_t sa = sb + SA2(stage);
    uint32_t sbB = sb + SB2(stage);
    int l15 = lane & 15, l16 = lane >> 4;
#pragma unroll
    for (int half = 0; half < 2; half++) {
        uint32_t ah[4][4];
#pragma unroll
        for (int mt = 0; mt < 4; mt++) {
            int row = wm * 64 + mt * 16 + l15;
            LDSM_X4(ah[mt][0], ah[mt][1], ah[mt][2], ah[mt][3],
                    sa + a_off64(row, half * 2 + l16));
        }
        uint32_t bf[8][2];
        int kk = half * 16 + l15;
#pragma unroll
        for (int ng = 0; ng < 4; ng++) {
            uint32_t off = b_off(kk, wn * 8 + ng * 2 + l16);
            LDSM_X4T(bf[2 * ng][0], bf[2 * ng][1],
                     bf[2 * ng + 1][0], bf[2 * ng + 1][1], sbB + off);
        }
#pragma unroll
        for (int mt = 0; mt < 4; mt++)
#pragma unroll
            for (int nt = 0; nt < 8; nt++)
                mma_f16(acc[mt][nt], ah[mt], bf[nt][0], bf[nt][1]);
    }
}

// ---------------- launch 0: init counters (must precede gating atomics) ------
__global__ void init_kernel() {
    if (threadIdx.x < NE) g_cnt[threadIdx.x] = 0;
}

// ---------------- launch 1: fused prologue -----------------------------------
#define GATE_BLOCKS 2048
#define ZERO_BLOCKS 16384
#define CONV_BLOCKS 32768
#define FUSED_BLOCKS (GATE_BLOCKS + ZERO_BLOCKS + 2 * CONV_BLOCKS)

__global__ __launch_bounds__(256) void fused_prep_kernel(
    const float* __restrict__ x, const float* __restrict__ gW,
    const float* __restrict__ gb, const float* __restrict__ W1,
    const float* __restrict__ W2, float* __restrict__ out, int write_topi) {
    int blk = blockIdx.x;
    if (blk < GATE_BLOCKS) {
        // ---- gating: one warp per token ----
        int warp = blk * 8 + (threadIdx.x >> 5);
        int lane = threadIdx.x & 31;
        const float* xr = x + (size_t)warp * DM;
        float acc[NE];
#pragma unroll
        for (int e = 0; e < NE; e++) acc[e] = 0.f;
        for (int d = lane; d < DM; d += 32) {
            float xv = xr[d];
            const float4* w4 = (const float4*)(gW + d * NE);
            float4 wa = w4[0], wb = w4[1];
            acc[0] += xv * wa.x; acc[1] += xv * wa.y;
            acc[2] += xv * wa.z; acc[3] += xv * wa.w;
            acc[4] += xv * wb.x; acc[5] += xv * wb.y;
            acc[6] += xv * wb.z; acc[7] += xv * wb.w;
        }
#pragma unroll
        for (int e = 0; e < NE; e++)
#pragma unroll
            for (int o = 16; o > 0; o >>= 1)
                acc[e] += __shfl_xor_sync(0xffffffffu, acc[e], o);
        int i0 = 0, i1 = 0, p0 = 0, p1 = 0;
        if (lane == 0) {
            float v0 = -1e30f, v1 = -1e30f;
#pragma unroll
            for (int e = 0; e < NE; e++) {
                float l = acc[e] + gb[e];
                if (l > v0)      { v1 = v0; i1 = i0; v0 = l; i0 = e; }
                else if (l > v1) { v1 = l;  i1 = e; }
            }
            float e1 = expf(v1 - v0);
            float s  = 1.f + e1;
            float w0 = 1.f / s, w1 = e1 / s;
            p0 = atomicAdd(&g_cnt[i0], 1);
            g_tok[i0 * NTOK + p0] = warp; g_wt[i0 * NTOK + p0] = w0;
            p1 = atomicAdd(&g_cnt[i1], 1);
            g_tok[i1 * NTOK + p1] = warp; g_wt[i1 * NTOK + p1] = w1;
            if (write_topi) {
                out[(size_t)NTOK * DM + warp * 2 + 0] = (float)i0;
                out[(size_t)NTOK * DM + warp * 2 + 1] = (float)i1;
            }
        }
        i0 = __shfl_sync(0xffffffffu, i0, 0); p0 = __shfl_sync(0xffffffffu, p0, 0);
        i1 = __shfl_sync(0xffffffffu, i1, 0); p1 = __shfl_sync(0xffffffffu, p1, 0);
        uint2* d0 = (uint2*)(XGH + ((size_t)i0 * NTOK + p0) * DM);
        uint2* d1 = (uint2*)(XGH + ((size_t)i1 * NTOK + p1) * DM);
        const float4* x4 = (const float4*)xr;
#pragma unroll
        for (int j = 0; j < DM / 128; j++) {
            int f = lane + 32 * j;
            float4 v = x4[f];
            uint2 hh;
            hh.x = pack_h2(v.x, v.y); hh.y = pack_h2(v.z, v.w);
            d0[f] = hh; d1[f] = hh;
        }
    } else if (blk < GATE_BLOCKS + ZERO_BLOCKS) {
        // ---- zero out[NTOK*DM] ----
        size_t i = (size_t)(blk - GATE_BLOCKS) * 256 + threadIdx.x;
        ((float4*)out)[i] = make_float4(0.f, 0.f, 0.f, 0.f);
    } else {
        // ---- weight fp32 -> fp16 convert ----
        int cblk = blk - GATE_BLOCKS - ZERO_BLOCKS;
        const float* src = (cblk < CONV_BLOCKS) ? W1 : W2;
        __half* dh = (cblk < CONV_BLOCKS) ? W1H : W2H;
        size_t i = (size_t)(cblk % CONV_BLOCKS) * 256 + threadIdx.x;
        float4 v = ((const float4*)src)[i];
        uint2 hh;
        hh.x = pack_h2(v.x, v.y); hh.y = pack_h2(v.z, v.w);
        ((uint2*)dh)[i] = hh;
    }
}

// ---------------- launch 2: GEMM1 (BK=64, 3 stages, 256 thr) -----------------
__global__ __launch_bounds__(THREADS1, 2) void gemm1_mma(const float* __restrict__ b1) {
    extern __shared__ char smem[];
    int e = blockIdx.z;
    int rows = g_cnt[e];
    int row0 = blockIdx.y * BM;
    if (row0 >= rows) return;
    int n0 = blockIdx.x * BN;
    uint32_t sb = (uint32_t)__cvta_generic_to_shared(smem);
    int tid = threadIdx.x, lane = tid & 31, wid = tid >> 5;
    int wm = wid & 1, wn = wid >> 1;
    const __half* B = W1H + (size_t)e * DM * DFFN;
    size_t arow0 = (size_t)e * NTOK + row0;

    float acc[4][4][4];
#pragma unroll
    for (int a = 0; a < 4; a++)
#pragma unroll
        for (int b = 0; b < 4; b++)
#pragma unroll
            for (int c = 0; c < 4; c++) acc[a][b][c] = 0.f;

    const int nk = DM / BK1;  // 16
#pragma unroll
    for (int p = 0; p < STAGES1 - 1; p++) {
        load_stage1(sb, p, XGH, DM, B, DFFN, arow0, p * BK1, n0, tid);
        CP_COMMIT();
    }
    // fully unrolled: stage indices & swizzle math become compile-time
#pragma unroll
    for (int t = 0; t < nk; t++) {
        CP_WAIT(STAGES1 - 2);
        __syncthreads();
        int nx = t + STAGES1 - 1;
        if (nx < nk)
            load_stage1(sb, nx % STAGES1, XGH, DM, B, DFFN,
                        arow0, nx * BK1, n0, tid);
        CP_COMMIT();
        compute_stage_a(sb, t % STAGES1, acc, wm, wn, lane);
    }

    const float* bias = b1 + (size_t)e * DFFN;
    int quad = lane >> 2, pair = lane & 3;
#pragma unroll
    for (int mt = 0; mt < 4; mt++) {
        int rb = row0 + wm * 64 + mt * 16 + quad;
#pragma unroll
        for (int nt = 0; nt < 4; nt++) {
            int col = n0 + wn * 32 + nt * 8 + pair * 2;
            float bs0 = __ldg(&bias[col]), bs1 = __ldg(&bias[col + 1]);
            if (rb < rows) {
                size_t o = ((size_t)e * NTOK + rb) * DFFN + col;
                *(uint32_t*)(HH + o) =
                    pack_h2(gelu_f(acc[mt][nt][0] + bs0), gelu_f(acc[mt][nt][1] + bs1));
            }
            if (rb + 8 < rows) {
                size_t o = ((size_t)e * NTOK + rb + 8) * DFFN + col;
                *(uint32_t*)(HH + o) =
                    pack_h2(gelu_f(acc[mt][nt][2] + bs0), gelu_f(acc[mt][nt][3] + bs1));
            }
        }
    }
}

// ---------------- launch 3: GEMM2 (BK=32, 4 stages, 128 thr) -----------------
__global__ __launch_bounds__(THREADS2, 2) void gemm2_mma(
    const float* __restrict__ b2, float* __restrict__ out) {
    extern __shared__ char smem[];
    int e = blockIdx.z;
    int rows = g_cnt[e];
    int row0 = blockIdx.y * BM;
    if (row0 >= rows) return;
    int n0 = blockIdx.x * BN;
    uint32_t sb = (uint32_t)__cvta_generic_to_shared(smem);
    int tid = threadIdx.x, lane = tid & 31, wid = tid >> 5;
    int wm = wid & 1, wn = wid >> 1;
    const __half* B = W2H + (size_t)e * DFFN * DM;
    size_t arow0 = (size_t)e * NTOK + row0;

    float acc[4][8][4];
#pragma unroll
    for (int a = 0; a < 4; a++)
#pragma unroll
        for (int b = 0; b < 8; b++)
#pragma unroll
            for (int c = 0; c < 4; c++) acc[a][b][c] = 0.f;

    const int nk = DFFN / BK2;  // 128
#pragma unroll
    for (int p = 0; p < STAGES2 - 1; p++) {
        load_stage2(sb, p, HH, DFFN, B, DM, arow0, p * BK2, n0, tid);
        CP_COMMIT();
    }
    // unroll one full stage period: stage = t & 3 becomes compile-time per slot
#pragma unroll 4
    for (int t = 0; t < nk; t++) {
        CP_WAIT(STAGES2 - 2);
        __syncthreads();
        int nx = t + STAGES2 - 1;
        if (nx < nk)
            load_stage2(sb, nx & (STAGES2 - 1), HH, DFFN, B, DM,
                        arow0, nx * BK2, n0, tid);
        CP_COMMIT();
        compute_stage_b(sb, t & (STAGES2 - 1), acc, wm, wn, lane);
    }

    const float* bias = b2 + (size_t)e * DM;
    int quad = lane >> 2, pair = lane & 3;
#pragma unroll
    for (int mt = 0; mt < 4; mt++) {
        int rb = row0 + wm * 64 + mt * 16 + quad;
        int tok0 = 0, tok1 = 0; float wt0 = 0.f, wt1 = 0.f;
        if (rb < rows)     { tok0 = g_tok[e * NTOK + rb];     wt0 = g_wt[e * NTOK + rb]; }
        if (rb + 8 < rows) { tok1 = g_tok[e * NTOK + rb + 8]; wt1 = g_wt[e * NTOK + rb + 8]; }
#pragma unroll
        for (int nt = 0; nt < 8; nt++) {
            int col = n0 + wn * 64 + nt * 8 + pair * 2;
            float bs0 = __ldg(&bias[col]), bs1 = __ldg(&bias[col + 1]);
            if (rb < rows) {
                float* orow = out + (size_t)tok0 * DM + col;
                red_add_v2(orow, (acc[mt][nt][0] + bs0) * wt0,
                                 (acc[mt][nt][1] + bs1) * wt0);
            }
            if (rb + 8 < rows) {
                float* orow = out + (size_t)tok1 * DM + col;
                red_add_v2(orow, (acc[mt][nt][2] + bs0) * wt1,
                                 (acc[mt][nt][3] + bs1) * wt1);
            }
        }
    }
}

// ---------------- host -------------------------------------------------------
extern "C" void kernel_launch(void* const* d_in, const int* in_sizes, int n_in,
                              void* d_out, int out_size) {
    const float* x  = (const float*)d_in[0];
    const float* gW = (const float*)d_in[1];
    const float* gb = (const float*)d_in[2];
    const float* W1 = (const float*)d_in[3];
    const float* b1 = (const float*)d_in[4];
    const float* W2 = (const float*)d_in[5];
    const float* b2 = (const float*)d_in[6];
    float* out = (float*)d_out;
    int write_topi = (out_size >= NTOK * DM + NTOK * TOPK) ? 1 : 0;

    cudaFuncSetAttribute(gemm1_mma, cudaFuncAttributeMaxDynamicSharedMemorySize, SMEM1);
    cudaFuncSetAttribute(gemm2_mma, cudaFuncAttributeMaxDynamicSharedMemorySize, SMEM2);

    // launch 0: counter init only (tiny)
    init_kernel<<<1, 32>>>();
    // launch 1: fused gating+scatter / out-zero / weight-convert
    fused_prep_kernel<<<FUSED_BLOCKS, 256>>>(x, gW, gb, W1, W2, out, write_topi);
    // launch 2: GEMM1, BK=64 / 3 stages, fully unrolled k-loop
    gemm1_mma<<<dim3(DFFN / BN, NTOK / BM, NE), THREADS1, SMEM1>>>(b1);
    // launch 3: GEMM2, BK=32 / 4 stages, period-unrolled k-loop
    gemm2_mma<<<dim3(DM / BN, NTOK / BM, NE), THREADS2, SMEM2>>>(b2, out);
}

// round 17
// speedup vs baseline: 1.1707x; 1.0118x over previous
#include <cuda_runtime.h>
#include <cuda_fp16.h>
#include <cstdint>
#include <math.h>

#define NTOK 16384
#define DM   1024
#define DFFN 4096
#define NE   8
#define TOPK 2

#define BM 128
#define BN 128
// gemm1: BK=64, 3 stages, 256 thr (warp grid 2x4, tile 64x32)
#define BK1 64
#define STAGES1 3
#define THREADS1 256
// gemm2: BK=32, 4 stages, 128 thr (warp grid 2x2, tile 64x64)
#define BK2 32
#define STAGES2 4
#define THREADS2 128

// ---------------- device scratch (static globals: allocation-free) ----------
__device__ int   g_cnt[NE];
__device__ int   g_tok[NE * NTOK];
__device__ float g_wt [NE * NTOK];

// per-expert strided layouts (slot = e*NTOK + r); pad rows never written -> 0
__device__ __align__(16) __half XGH[((size_t)NE * NTOK + BM) * DM];
__device__ __align__(16) __half HH [((size_t)NE * NTOK + BM) * DFFN];
__device__ __align__(16) __half W1H[(size_t)NE * DM * DFFN];
__device__ __align__(16) __half W2H[(size_t)NE * DFFN * DM];

// ---------------- asm helpers ----------------------------------------------
__device__ __forceinline__ void cp16(uint32_t dst, const void* src) {
    asm volatile("cp.async.cg.shared.global [%0], [%1], 16;" :: "r"(dst), "l"(src));
}
#define CP_COMMIT() asm volatile("cp.async.commit_group;" ::: "memory")
#define CP_WAIT(n)  asm volatile("cp.async.wait_group %0;" :: "n"(n) : "memory")

#define LDSM_X4(r0, r1, r2, r3, addr) \
    asm volatile("ldmatrix.sync.aligned.m8n8.x4.shared.b16 {%0,%1,%2,%3}, [%4];" \
                 : "=r"(r0), "=r"(r1), "=r"(r2), "=r"(r3) : "r"(addr))
#define LDSM_X4T(r0, r1, r2, r3, addr) \
    asm volatile("ldmatrix.sync.aligned.m8n8.x4.trans.shared.b16 {%0,%1,%2,%3}, [%4];" \
                 : "=r"(r0), "=r"(r1), "=r"(r2), "=r"(r3) : "r"(addr))

__device__ __forceinline__ void mma_f16(float* c, const uint32_t* a,
                                        uint32_t b0, uint32_t b1) {
    asm volatile(
        "mma.sync.aligned.m16n8k16.row.col.f32.f16.f16.f32 "
        "{%0,%1,%2,%3}, {%4,%5,%6,%7}, {%8,%9}, {%0,%1,%2,%3};"
        : "+f"(c[0]), "+f"(c[1]), "+f"(c[2]), "+f"(c[3])
        : "r"(a[0]), "r"(a[1]), "r"(a[2]), "r"(a[3]), "r"(b0), "r"(b1));
}

// vector reduction (sm_90+): one instruction adds 2 floats to gmem
__device__ __forceinline__ void red_add_v2(float* addr, float y0, float y1) {
    asm volatile("red.global.add.v2.f32 [%0], {%1, %2};"
                 :: "l"(addr), "f"(y0), "f"(y1) : "memory");
}

// ---------------- smem layouts -----------------------------------------------
#define STG1 32768u
#define SA1(s) ((uint32_t)(s) * STG1)
#define SB1(s) ((uint32_t)(s) * STG1 + 16384u)
#define SMEM1  (STAGES1 * 32768)
#define STG2 16384u
#define SA2(s) ((uint32_t)(s) * STG2)
#define SB2(s) ((uint32_t)(s) * STG2 + 8192u)
#define SMEM2  (STAGES2 * 16384)

// A swizzles: conflict-free for their row pitches
__device__ __forceinline__ uint32_t a_off128(int row, int ch) {   // pitch 128B
    return (uint32_t)(row * 128 + ((ch ^ (row & 7)) << 4));
}
__device__ __forceinline__ uint32_t a_off64(int row, int ch) {    // pitch 64B
    return (uint32_t)(row * 64 + ((ch ^ ((row >> 1) & 3)) << 4));
}
// B: row pitch 256B (16x16B chunks), swizzle low3 of chunk ^= k&7
__device__ __forceinline__ uint32_t b_off(int k, int ch) {
    return (uint32_t)(k * 256 + (((ch & ~7) | ((ch ^ k) & 7)) << 4));
}

__device__ __forceinline__ float gelu_f(float v) {
    return 0.5f * v * (1.f + erff(v * 0.70710678118654752440f));
}
__device__ __forceinline__ uint32_t pack_h2(float a, float b) {
    __half x = __float2half_rn(a), y = __float2half_rn(b);
    return (uint32_t)__half_as_ushort(x) | ((uint32_t)__half_as_ushort(y) << 16);
}

// ---------------- stage loaders ----------------------------------------------
__device__ __forceinline__ void load_stage1(
    uint32_t sb, int stage, const __half* __restrict__ A, size_t lda,
    const __half* __restrict__ B, size_t ldb,
    size_t arow0, int k0, int n0, int tid) {
#pragma unroll
    for (int i = 0; i < 4; i++) {           // A: 1024 chunks (128 rows x 8)
        int ca = tid + THREADS1 * i;
        int row = ca >> 3, ch = ca & 7;
        size_t gsrc = (arow0 + row) * lda + k0 + ch * 8;
        cp16(sb + SA1(stage) + a_off128(row, ch), A + gsrc);
    }
#pragma unroll
    for (int i = 0; i < 4; i++) {           // B: 1024 chunks (64 k x 16)
        int cb = tid + THREADS1 * i;
        int k = cb >> 4, ch = cb & 15;
        size_t gsrc = (size_t)(k0 + k) * ldb + n0 + ch * 8;
        cp16(sb + SB1(stage) + b_off(k, ch), B + gsrc);
    }
}
__device__ __forceinline__ void load_stage2(
    uint32_t sb, int stage, const __half* __restrict__ A, size_t lda,
    const __half* __restrict__ B, size_t ldb,
    size_t arow0, int k0, int n0, int tid) {
#pragma unroll
    for (int i = 0; i < 4; i++) {           // A: 512 chunks (128 rows x 4)
        int ca = tid + THREADS2 * i;
        int row = ca >> 2, ch = ca & 3;
        size_t gsrc = (arow0 + row) * lda + k0 + ch * 8;
        cp16(sb + SA2(stage) + a_off64(row, ch), A + gsrc);
    }
#pragma unroll
    for (int i = 0; i < 4; i++) {           // B: 512 chunks (32 k x 16)
        int cb = tid + THREADS2 * i;
        int k = cb >> 4, ch = cb & 15;
        size_t gsrc = (size_t)(k0 + k) * ldb + n0 + ch * 8;
        cp16(sb + SB2(stage) + b_off(k, ch), B + gsrc);
    }
}

// ---------------- compute A: 8 warps, grid 2x4, warp tile 64x32, BK=64 ------
__device__ __forceinline__ void compute_stage_a(
    uint32_t sb, int stage, float acc[4][4][4], int wm, int wn, int lane) {
    uint32_t sa = sb + SA1(stage);
    uint32_t sbB = sb + SB1(stage);
    int l15 = lane & 15, l16 = lane >> 4;
#pragma unroll
    for (int half = 0; half < 4; half++) {
        uint32_t ah[4][4];
#pragma unroll
        for (int mt = 0; mt < 4; mt++) {
            int row = wm * 64 + mt * 16 + l15;
            LDSM_X4(ah[mt][0], ah[mt][1], ah[mt][2], ah[mt][3],
                    sa + a_off128(row, half * 2 + l16));
        }
        uint32_t bf[4][2];
        int kk = half * 16 + l15;
#pragma unroll
        for (int ng = 0; ng < 2; ng++) {
            uint32_t off = b_off(kk, wn * 4 + ng * 2 + l16);
            LDSM_X4T(bf[2 * ng][0], bf[2 * ng][1],
                     bf[2 * ng + 1][0], bf[2 * ng + 1][1], sbB + off);
        }
#pragma unroll
        for (int mt = 0; mt < 4; mt++)
#pragma unroll
            for (int nt = 0; nt < 4; nt++)
                mma_f16(acc[mt][nt], ah[mt], bf[nt][0], bf[nt][1]);
    }
}

// ---------------- compute B: 4 warps, grid 2x2, warp tile 64x64, BK=32 ------
__device__ __forceinline__ void compute_stage_b(
    uint32_t sb, int stage, float acc[4][8][4], int wm, int wn, int lane) {
    uint32_t sa = sb + SA2(stage);
    uint32_t sbB = sb + SB2(stage);
    int l15 = lane & 15, l16 = lane >> 4;
#pragma unroll
    for (int half = 0; half < 2; half++) {
        uint32_t ah[4][4];
#pragma unroll
        for (int mt = 0; mt < 4; mt++) {
            int row = wm * 64 + mt * 16 + l15;
            LDSM_X4(ah[mt][0], ah[mt][1], ah[mt][2], ah[mt][3],
                    sa + a_off64(row, half * 2 + l16));
        }
        uint32_t bf[8][2];
        int kk = half * 16 + l15;
#pragma unroll
        for (int ng = 0; ng < 4; ng++) {
            uint32_t off = b_off(kk, wn * 8 + ng * 2 + l16);
            LDSM_X4T(bf[2 * ng][0], bf[2 * ng][1],
                     bf[2 * ng + 1][0], bf[2 * ng + 1][1], sbB + off);
        }
#pragma unroll
        for (int mt = 0; mt < 4; mt++)
#pragma unroll
            for (int nt = 0; nt < 8; nt++)
                mma_f16(acc[mt][nt], ah[mt], bf[nt][0], bf[nt][1]);
    }
}

// ---------------- launch 0: init counters (must precede gating atomics) ------
__global__ void init_kernel() {
    if (threadIdx.x < NE) g_cnt[threadIdx.x] = 0;
}

// ---------------- launch 1: prep = gating+scatter + W1 convert ---------------
#define GATE_BLOCKS 2048
#define CONV_BLOCKS 32768
#define PREP_BLOCKS (GATE_BLOCKS + CONV_BLOCKS)

__global__ __launch_bounds__(256) void prep_kernel(
    const float* __restrict__ x, const float* __restrict__ gW,
    const float* __restrict__ gb, const float* __restrict__ W1,
    float* __restrict__ out, int write_topi) {
    int blk = blockIdx.x;
    if (blk < GATE_BLOCKS) {
        // ---- gating: one warp per token ----
        int warp = blk * 8 + (threadIdx.x >> 5);
        int lane = threadIdx.x & 31;
        const float* xr = x + (size_t)warp * DM;
        float acc[NE];
#pragma unroll
        for (int e = 0; e < NE; e++) acc[e] = 0.f;
        for (int d = lane; d < DM; d += 32) {
            float xv = xr[d];
            const float4* w4 = (const float4*)(gW + d * NE);
            float4 wa = w4[0], wb = w4[1];
            acc[0] += xv * wa.x; acc[1] += xv * wa.y;
            acc[2] += xv * wa.z; acc[3] += xv * wa.w;
            acc[4] += xv * wb.x; acc[5] += xv * wb.y;
            acc[6] += xv * wb.z; acc[7] += xv * wb.w;
        }
#pragma unroll
        for (int e = 0; e < NE; e++)
#pragma unroll
            for (int o = 16; o > 0; o >>= 1)
                acc[e] += __shfl_xor_sync(0xffffffffu, acc[e], o);
        int i0 = 0, i1 = 0, p0 = 0, p1 = 0;
        if (lane == 0) {
            float v0 = -1e30f, v1 = -1e30f;
#pragma unroll
            for (int e = 0; e < NE; e++) {
                float l = acc[e] + gb[e];
                if (l > v0)      { v1 = v0; i1 = i0; v0 = l; i0 = e; }
                else if (l > v1) { v1 = l;  i1 = e; }
            }
            float e1 = expf(v1 - v0);
            float s  = 1.f + e1;
            float w0 = 1.f / s, w1 = e1 / s;
            p0 = atomicAdd(&g_cnt[i0], 1);
            g_tok[i0 * NTOK + p0] = warp; g_wt[i0 * NTOK + p0] = w0;
            p1 = atomicAdd(&g_cnt[i1], 1);
            g_tok[i1 * NTOK + p1] = warp; g_wt[i1 * NTOK + p1] = w1;
            if (write_topi) {
                out[(size_t)NTOK * DM + warp * 2 + 0] = (float)i0;
                out[(size_t)NTOK * DM + warp * 2 + 1] = (float)i1;
            }
        }
        i0 = __shfl_sync(0xffffffffu, i0, 0); p0 = __shfl_sync(0xffffffffu, p0, 0);
        i1 = __shfl_sync(0xffffffffu, i1, 0); p1 = __shfl_sync(0xffffffffu, p1, 0);
        uint2* d0 = (uint2*)(XGH + ((size_t)i0 * NTOK + p0) * DM);
        uint2* d1 = (uint2*)(XGH + ((size_t)i1 * NTOK + p1) * DM);
        const float4* x4 = (const float4*)xr;
#pragma unroll
        for (int j = 0; j < DM / 128; j++) {
            int f = lane + 32 * j;
            float4 v = x4[f];
            uint2 hh;
            hh.x = pack_h2(v.x, v.y); hh.y = pack_h2(v.z, v.w);
            d0[f] = hh; d1[f] = hh;
        }
    } else {
        // ---- W1 fp32 -> fp16 convert ----
        size_t i = (size_t)(blk - GATE_BLOCKS) * 256 + threadIdx.x;
        float4 v = ((const float4*)W1)[i];
        uint2 hh;
        hh.x = pack_h2(v.x, v.y); hh.y = pack_h2(v.z, v.w);
        ((uint2*)W1H)[i] = hh;
    }
}

// ---------------- launch 2: GEMM1 + aux slice (W2 convert, out zero) ---------
// grid (32, 128, 9): z=0 -> aux DRAM work overlapped with gemm1; z>=1 -> e=z-1
__global__ __launch_bounds__(THREADS1, 2) void gemm1_mma(
    const float* __restrict__ b1, const float* __restrict__ W2,
    float* __restrict__ out) {
    extern __shared__ char smem[];
    if (blockIdx.z == 0) {
        // aux: 4096 blocks x 256 threads
        size_t base = ((size_t)blockIdx.y * 32 + blockIdx.x) * 256 + threadIdx.x;
#pragma unroll
        for (int j = 0; j < 8; j++) {           // W2: 8.39M float4 total
            size_t i = base + (size_t)j * 1048576;
            float4 v = ((const float4*)W2)[i];
            uint2 hh;
            hh.x = pack_h2(v.x, v.y); hh.y = pack_h2(v.z, v.w);
            ((uint2*)W2H)[i] = hh;
        }
#pragma unroll
        for (int j = 0; j < 4; j++) {           // zero out: 4.19M float4
            size_t i = base + (size_t)j * 1048576;
            ((float4*)out)[i] = make_float4(0.f, 0.f, 0.f, 0.f);
        }
        return;
    }
    int e = blockIdx.z - 1;
    int rows = g_cnt[e];
    int row0 = blockIdx.y * BM;
    if (row0 >= rows) return;
    int n0 = blockIdx.x * BN;
    uint32_t sb = (uint32_t)__cvta_generic_to_shared(smem);
    int tid = threadIdx.x, lane = tid & 31, wid = tid >> 5;
    int wm = wid & 1, wn = wid >> 1;
    const __half* B = W1H + (size_t)e * DM * DFFN;
    size_t arow0 = (size_t)e * NTOK + row0;

    float acc[4][4][4];
#pragma unroll
    for (int a = 0; a < 4; a++)
#pragma unroll
        for (int b = 0; b < 4; b++)
#pragma unroll
            for (int c = 0; c < 4; c++) acc[a][b][c] = 0.f;

    const int nk = DM / BK1;  // 16
#pragma unroll
    for (int p = 0; p < STAGES1 - 1; p++) {
        load_stage1(sb, p, XGH, DM, B, DFFN, arow0, p * BK1, n0, tid);
        CP_COMMIT();
    }
    // fully unrolled: stage indices & swizzle math become compile-time
#pragma unroll
    for (int t = 0; t < nk; t++) {
        CP_WAIT(STAGES1 - 2);
        __syncthreads();
        int nx = t + STAGES1 - 1;
        if (nx < nk)
            load_stage1(sb, nx % STAGES1, XGH, DM, B, DFFN,
                        arow0, nx * BK1, n0, tid);
        CP_COMMIT();
        compute_stage_a(sb, t % STAGES1, acc, wm, wn, lane);
    }

    const float* bias = b1 + (size_t)e * DFFN;
    int quad = lane >> 2, pair = lane & 3;
#pragma unroll
    for (int mt = 0; mt < 4; mt++) {
        int rb = row0 + wm * 64 + mt * 16 + quad;
#pragma unroll
        for (int nt = 0; nt < 4; nt++) {
            int col = n0 + wn * 32 + nt * 8 + pair * 2;
            float bs0 = __ldg(&bias[col]), bs1 = __ldg(&bias[col + 1]);
            if (rb < rows) {
                size_t o = ((size_t)e * NTOK + rb) * DFFN + col;
                *(uint32_t*)(HH + o) =
                    pack_h2(gelu_f(acc[mt][nt][0] + bs0), gelu_f(acc[mt][nt][1] + bs1));
            }
            if (rb + 8 < rows) {
                size_t o = ((size_t)e * NTOK + rb + 8) * DFFN + col;
                *(uint32_t*)(HH + o) =
                    pack_h2(gelu_f(acc[mt][nt][2] + bs0), gelu_f(acc[mt][nt][3] + bs1));
            }
        }
    }
}

// ---------------- launch 3: GEMM2 (BK=32, 4 stages, 128 thr) -----------------
__global__ __launch_bounds__(THREADS2, 2) void gemm2_mma(
    const float* __restrict__ b2, float* __restrict__ out) {
    extern __shared__ char smem[];
    int e = blockIdx.z;
    int rows = g_cnt[e];
    int row0 = blockIdx.y * BM;
    if (row0 >= rows) return;
    int n0 = blockIdx.x * BN;
    uint32_t sb = (uint32_t)__cvta_generic_to_shared(smem);
    int tid = threadIdx.x, lane = tid & 31, wid = tid >> 5;
    int wm = wid & 1, wn = wid >> 1;
    const __half* B = W2H + (size_t)e * DFFN * DM;
    size_t arow0 = (size_t)e * NTOK + row0;

    float acc[4][8][4];
#pragma unroll
    for (int a = 0; a < 4; a++)
#pragma unroll
        for (int b = 0; b < 8; b++)
#pragma unroll
            for (int c = 0; c < 4; c++) acc[a][b][c] = 0.f;

    const int nk = DFFN / BK2;  // 128
#pragma unroll
    for (int p = 0; p < STAGES2 - 1; p++) {
        load_stage2(sb, p, HH, DFFN, B, DM, arow0, p * BK2, n0, tid);
        CP_COMMIT();
    }
    // unroll one full stage period: stage = t & 3 becomes compile-time per slot
#pragma unroll 4
    for (int t = 0; t < nk; t++) {
        CP_WAIT(STAGES2 - 2);
        __syncthreads();
        int nx = t + STAGES2 - 1;
        if (nx < nk)
            load_stage2(sb, nx & (STAGES2 - 1), HH, DFFN, B, DM,
                        arow0, nx * BK2, n0, tid);
        CP_COMMIT();
        compute_stage_b(sb, t & (STAGES2 - 1), acc, wm, wn, lane);
    }

    const float* bias = b2 + (size_t)e * DM;
    int quad = lane >> 2, pair = lane & 3;
#pragma unroll
    for (int mt = 0; mt < 4; mt++) {
        int rb = row0 + wm * 64 + mt * 16 + quad;
        int tok0 = 0, tok1 = 0; float wt0 = 0.f, wt1 = 0.f;
        if (rb < rows)     { tok0 = g_tok[e * NTOK + rb];     wt0 = g_wt[e * NTOK + rb]; }
        if (rb + 8 < rows) { tok1 = g_tok[e * NTOK + rb + 8]; wt1 = g_wt[e * NTOK + rb + 8]; }
#pragma unroll
        for (int nt = 0; nt < 8; nt++) {
            int col = n0 + wn * 64 + nt * 8 + pair * 2;
            float bs0 = __ldg(&bias[col]), bs1 = __ldg(&bias[col + 1]);
            if (rb < rows) {
                float* orow = out + (size_t)tok0 * DM + col;
                red_add_v2(orow, (acc[mt][nt][0] + bs0) * wt0,
                                 (acc[mt][nt][1] + bs1) * wt0);
            }
            if (rb + 8 < rows) {
                float* orow = out + (size_t)tok1 * DM + col;
                red_add_v2(orow, (acc[mt][nt][2] + bs0) * wt1,
                                 (acc[mt][nt][3] + bs1) * wt1);
            }
        }
    }
}

// ---------------- host -------------------------------------------------------
extern "C" void kernel_launch(void* const* d_in, const int* in_sizes, int n_in,
                              void* d_out, int out_size) {
    const float* x  = (const float*)d_in[0];
    const float* gW = (const float*)d_in[1];
    const float* gb = (const float*)d_in[2];
    const float* W1 = (const float*)d_in[3];
    const float* b1 = (const float*)d_in[4];
    const float* W2 = (const float*)d_in[5];
    const float* b2 = (const float*)d_in[6];
    float* out = (float*)d_out;
    int write_topi = (out_size >= NTOK * DM + NTOK * TOPK) ? 1 : 0;

    cudaFuncSetAttribute(gemm1_mma, cudaFuncAttributeMaxDynamicSharedMemorySize, SMEM1);
    cudaFuncSetAttribute(gemm2_mma, cudaFuncAttributeMaxDynamicSharedMemorySize, SMEM2);

    // launch 0: counter init only (tiny)
    init_kernel<<<1, 32>>>();
    // launch 1: gating+scatter + W1 convert (only true gemm1 dependencies)
    prep_kernel<<<PREP_BLOCKS, 256>>>(x, gW, gb, W1, out, write_topi);
    // launch 2: GEMM1 + overlapped aux slice (W2 convert + out zero) at z=0
    gemm1_mma<<<dim3(DFFN / BN, NTOK / BM, NE + 1), THREADS1, SMEM1>>>(b1, W2, out);
    // launch 3: GEMM2
    gemm2_mma<<<dim3(DM / BN, NTOK / BM, NE), THREADS2, SMEM2>>>(b2, out);
}